// round 1
// baseline (speedup 1.0000x reference)
#include <cuda_runtime.h>
#include <math.h>

#define B_    2
#define S_    2048
#define D_    1024
#define H_    16
#define KS_   64
#define QKV_  192
#define NQKV  (H_ * QKV_)   /* 3072 */
#define MROWS (B_ * S_)     /* 4096 */

// Scratch (allocation-free rule: __device__ globals)
__device__ float g_qkv[(size_t)MROWS * NQKV];  // ~50 MB
__device__ float g_att[(size_t)MROWS * D_];    // ~17 MB
__device__ float g_y[(size_t)MROWS * D_];      // ~17 MB

// ---------------------------------------------------------------------------
// SGEMM: C[M,N] = A[M,K] @ B[K,N], row-major. M%64==0, N%64==0, K%16==0.
// 64x64 block tile, 256 threads, 4x4 per thread, K-step 16.
// ---------------------------------------------------------------------------
__global__ void __launch_bounds__(256) sgemm64(const float* __restrict__ A,
                                               const float* __restrict__ Bm,
                                               float* __restrict__ C,
                                               int M, int N, int K) {
    __shared__ __align__(16) float As[16][64];   // k-major: As[k][m]
    __shared__ __align__(16) float Bs[16][64];   // Bs[k][n]

    const int tx = threadIdx.x & 15;
    const int ty = threadIdx.x >> 4;
    const int m0 = blockIdx.y * 64;
    const int n0 = blockIdx.x * 64;

    const int la_row = threadIdx.x >> 2;          // 0..63
    const int la_col = (threadIdx.x & 3) * 4;     // 0..12
    const int lb_row = threadIdx.x >> 4;          // 0..15
    const int lb_col = (threadIdx.x & 15) * 4;    // 0..60

    float acc[4][4] = {};

    for (int k0 = 0; k0 < K; k0 += 16) {
        float4 av = *(const float4*)&A[(size_t)(m0 + la_row) * K + k0 + la_col];
        float4 bv = *(const float4*)&Bm[(size_t)(k0 + lb_row) * N + n0 + lb_col];
        __syncthreads();
        As[la_col + 0][la_row] = av.x;
        As[la_col + 1][la_row] = av.y;
        As[la_col + 2][la_row] = av.z;
        As[la_col + 3][la_row] = av.w;
        *(float4*)&Bs[lb_row][lb_col] = bv;
        __syncthreads();
#pragma unroll
        for (int kk = 0; kk < 16; kk++) {
            float4 a4 = *(const float4*)&As[kk][ty * 4];
            float4 b4 = *(const float4*)&Bs[kk][tx * 4];
            float ar[4] = {a4.x, a4.y, a4.z, a4.w};
            float br[4] = {b4.x, b4.y, b4.z, b4.w};
#pragma unroll
            for (int i = 0; i < 4; i++)
#pragma unroll
                for (int j = 0; j < 4; j++)
                    acc[i][j] += ar[i] * br[j];
        }
    }

#pragma unroll
    for (int i = 0; i < 4; i++) {
        float4 cv = make_float4(acc[i][0], acc[i][1], acc[i][2], acc[i][3]);
        *(float4*)&C[(size_t)(m0 + ty * 4 + i) * N + n0 + tx * 4] = cv;
    }
}

// ---------------------------------------------------------------------------
// Attention with multiplicative tril mask semantics:
//   s = (k <= q) ? q.k * scale : 0 ;  softmax over ALL S keys ;  out = w @ V
// Flash-style online softmax; fully-masked tiles use exp(-m)*colsum(V).
// grid: (S/64, H, B); 128 threads; 64 KB dynamic smem.
// ---------------------------------------------------------------------------
__global__ void __launch_bounds__(128) attn_kernel(const float* __restrict__ qkv,
                                                   float* __restrict__ att) {
    extern __shared__ __align__(16) float sm[];
    float* Qs = sm;            // [64][64] d-major: Qs[d*64 + q]
    float* Ks = sm + 4096;     // [64][64] d-major: Ks[d*64 + k]
    float* Vs = sm + 8192;     // [64][64] key-major: Vs[k*64 + d]
    float* Ps = sm + 12288;    // [64][64] key-major: Ps[k*64 + q]

    const int tid   = threadIdx.x;
    const int lane  = tid & 31;
    const int warp  = tid >> 5;
    const int row_t = lane >> 3;       // 0..3
    const int col_t = lane & 7;        // 0..7
    const int r_base = warp * 16 + row_t * 4;   // 4 query rows
    const int c_base = col_t * 8;               // 8 cols (keys / out dims)

    const int q0 = blockIdx.x * 64;
    const int h  = blockIdx.y;
    const int b  = blockIdx.z;
    const size_t base = (size_t)b * S_ * NQKV + (size_t)h * QKV_;
    const float scale = 0.125f;   // 1/sqrt(64)

    // Load Q tile transposed (d-major)
    for (int i = tid; i < 1024; i += 128) {
        int q = i >> 4, dc = (i & 15) << 2;
        float4 v = *(const float4*)&qkv[base + (size_t)(q0 + q) * NQKV + dc];
        Qs[(dc + 0) * 64 + q] = v.x;
        Qs[(dc + 1) * 64 + q] = v.y;
        Qs[(dc + 2) * 64 + q] = v.z;
        Qs[(dc + 3) * 64 + q] = v.w;
    }

    float m[4], l[4], o[4][8];
#pragma unroll
    for (int r = 0; r < 4; r++) {
        m[r] = -1e30f;
        l[r] = 0.0f;
#pragma unroll
        for (int c = 0; c < 8; c++) o[r][c] = 0.0f;
    }

    for (int kt = 0; kt < S_ / 64; kt++) {
        const int k0 = kt * 64;
        const bool fully_masked = (k0 > q0 + 63);   // uniform across block

        __syncthreads();
        // Load V always; K only when scores are needed
        for (int i = tid; i < 1024; i += 128) {
            int kr = i >> 4, dc = (i & 15) << 2;
            const float* rowp = &qkv[base + (size_t)(k0 + kr) * NQKV];
            float4 vv = *(const float4*)&rowp[128 + dc];
            *(float4*)&Vs[kr * 64 + dc] = vv;
            if (!fully_masked) {
                float4 kv = *(const float4*)&rowp[64 + dc];
                Ks[(dc + 0) * 64 + kr] = kv.x;
                Ks[(dc + 1) * 64 + kr] = kv.y;
                Ks[(dc + 2) * 64 + kr] = kv.z;
                Ks[(dc + 3) * 64 + kr] = kv.w;
            }
        }
        __syncthreads();

        if (!fully_masked) {
            float s[4][8] = {};
#pragma unroll 4
            for (int d = 0; d < 64; d++) {
                float4 a  = *(const float4*)&Qs[d * 64 + r_base];
                float4 b0 = *(const float4*)&Ks[d * 64 + c_base];
                float4 b1 = *(const float4*)&Ks[d * 64 + c_base + 4];
                float ar[4] = {a.x, a.y, a.z, a.w};
                float br[8] = {b0.x, b0.y, b0.z, b0.w, b1.x, b1.y, b1.z, b1.w};
#pragma unroll
                for (int r = 0; r < 4; r++)
#pragma unroll
                    for (int c = 0; c < 8; c++)
                        s[r][c] += ar[r] * br[c];
            }
            // multiplicative mask + scale (masked logits are exactly 0)
#pragma unroll
            for (int r = 0; r < 4; r++) {
                int gq = q0 + r_base + r;
#pragma unroll
                for (int c = 0; c < 8; c++) {
                    int gk = k0 + c_base + c;
                    s[r][c] = (gk <= gq) ? s[r][c] * scale : 0.0f;
                }
            }
            // online softmax update (row stats shared across the 8 col-lanes)
#pragma unroll
            for (int r = 0; r < 4; r++) {
                float mt = s[r][0];
#pragma unroll
                for (int c = 1; c < 8; c++) mt = fmaxf(mt, s[r][c]);
                mt = fmaxf(mt, __shfl_xor_sync(0xffffffffu, mt, 1));
                mt = fmaxf(mt, __shfl_xor_sync(0xffffffffu, mt, 2));
                mt = fmaxf(mt, __shfl_xor_sync(0xffffffffu, mt, 4));
                float mn = fmaxf(m[r], mt);
                float alpha = __expf(m[r] - mn);
                m[r] = mn;
                float ls = 0.0f;
#pragma unroll
                for (int c = 0; c < 8; c++) {
                    s[r][c] = __expf(s[r][c] - mn);   // reuse s as p
                    ls += s[r][c];
                }
                l[r] = l[r] * alpha + ls;
#pragma unroll
                for (int c = 0; c < 8; c++) o[r][c] *= alpha;
            }
            // write P transposed (key-major) for vectorized PV
#pragma unroll
            for (int c = 0; c < 8; c++) {
                float4 pv = make_float4(s[0][c], s[1][c], s[2][c], s[3][c]);
                *(float4*)&Ps[(c_base + c) * 64 + r_base] = pv;
            }
            __syncthreads();
            // O += P @ V
#pragma unroll 4
            for (int kk = 0; kk < 64; kk++) {
                float4 pp = *(const float4*)&Ps[kk * 64 + r_base];
                float4 v0 = *(const float4*)&Vs[kk * 64 + c_base];
                float4 v1 = *(const float4*)&Vs[kk * 64 + c_base + 4];
                float pr[4] = {pp.x, pp.y, pp.z, pp.w};
                float vr[8] = {v0.x, v0.y, v0.z, v0.w, v1.x, v1.y, v1.z, v1.w};
#pragma unroll
                for (int r = 0; r < 4; r++)
#pragma unroll
                    for (int c = 0; c < 8; c++)
                        o[r][c] += pr[r] * vr[c];
            }
        } else {
            // scores are uniformly 0: contribution is exp(-m_new)*colsum(V)
            float vs[8] = {};
#pragma unroll 4
            for (int kk = 0; kk < 64; kk++) {
                float4 v0 = *(const float4*)&Vs[kk * 64 + c_base];
                float4 v1 = *(const float4*)&Vs[kk * 64 + c_base + 4];
                vs[0] += v0.x; vs[1] += v0.y; vs[2] += v0.z; vs[3] += v0.w;
                vs[4] += v1.x; vs[5] += v1.y; vs[6] += v1.z; vs[7] += v1.w;
            }
#pragma unroll
            for (int r = 0; r < 4; r++) {
                float mn = fmaxf(m[r], 0.0f);
                float alpha = __expf(m[r] - mn);
                float e0 = __expf(-mn);
                m[r] = mn;
                l[r] = l[r] * alpha + 8.0f * e0;   // 8 keys per lane per row
#pragma unroll
                for (int c = 0; c < 8; c++)
                    o[r][c] = o[r][c] * alpha + e0 * vs[c];
            }
        }
    }

    // finalize: reduce l over the 8 col-lanes, divide, store
#pragma unroll
    for (int r = 0; r < 4; r++) {
        float lt = l[r];
        lt += __shfl_xor_sync(0xffffffffu, lt, 1);
        lt += __shfl_xor_sync(0xffffffffu, lt, 2);
        lt += __shfl_xor_sync(0xffffffffu, lt, 4);
        float inv = 1.0f / lt;
        size_t orow = ((size_t)b * S_ + q0 + r_base + r) * D_ + h * 64 + c_base;
        float4 o0 = make_float4(o[r][0] * inv, o[r][1] * inv, o[r][2] * inv, o[r][3] * inv);
        float4 o1 = make_float4(o[r][4] * inv, o[r][5] * inv, o[r][6] * inv, o[r][7] * inv);
        *(float4*)&att[orow]     = o0;
        *(float4*)&att[orow + 4] = o1;
    }
}

// ---------------------------------------------------------------------------
// out = LayerNorm(x + y) * gamma + beta   (population var, eps = 1e-3)
// one block per row of 1024; 256 threads x 4 elements
// ---------------------------------------------------------------------------
__global__ void __launch_bounds__(256) ln_kernel(const float* __restrict__ x,
                                                 const float* __restrict__ y,
                                                 const float* __restrict__ gamma,
                                                 const float* __restrict__ beta,
                                                 float* __restrict__ out) {
    __shared__ float red[8];
    const int row = blockIdx.x;
    const int t = threadIdx.x;
    const int lane = t & 31, wid = t >> 5;
    const size_t off = (size_t)row * D_;

    float v[4];
    float s = 0.0f;
#pragma unroll
    for (int i = 0; i < 4; i++) {
        int idx = t + i * 256;
        v[i] = x[off + idx] + y[off + idx];
        s += v[i];
    }
    for (int d = 16; d > 0; d >>= 1) s += __shfl_xor_sync(0xffffffffu, s, d);
    if (lane == 0) red[wid] = s;
    __syncthreads();
    float tot = 0.0f;
#pragma unroll
    for (int w = 0; w < 8; w++) tot += red[w];
    const float mean = tot * (1.0f / D_);

    __syncthreads();
    float ss = 0.0f;
#pragma unroll
    for (int i = 0; i < 4; i++) {
        float d = v[i] - mean;
        ss += d * d;
    }
    for (int d = 16; d > 0; d >>= 1) ss += __shfl_xor_sync(0xffffffffu, ss, d);
    if (lane == 0) red[wid] = ss;
    __syncthreads();
    float tot2 = 0.0f;
#pragma unroll
    for (int w = 0; w < 8; w++) tot2 += red[w];
    const float rstd = rsqrtf(tot2 * (1.0f / D_) + 1e-3f);

#pragma unroll
    for (int i = 0; i < 4; i++) {
        int idx = t + i * 256;
        out[off + idx] = (v[i] - mean) * rstd * gamma[idx] + beta[idx];
    }
}

// ---------------------------------------------------------------------------
extern "C" void kernel_launch(void* const* d_in, const int* in_sizes, int n_in,
                              void* d_out, int out_size) {
    const float* x       = (const float*)d_in[0];
    // d_in[1] = mask (tril, multiplicative) — structure used analytically
    const float* W_embed = (const float*)d_in[2];
    const float* W_out   = (const float*)d_in[3];
    const float* gamma   = (const float*)d_in[4];
    const float* beta    = (const float*)d_in[5];
    float* out = (float*)d_out;

    float *qkv, *att, *y;
    cudaGetSymbolAddress((void**)&qkv, g_qkv);
    cudaGetSymbolAddress((void**)&att, g_att);
    cudaGetSymbolAddress((void**)&y,   g_y);

    cudaFuncSetAttribute(attn_kernel,
                         cudaFuncAttributeMaxDynamicSharedMemorySize, 65536);

    // 1) qkv = x @ W_embed   [4096 x 3072 x 1024]
    sgemm64<<<dim3(NQKV / 64, MROWS / 64), 256>>>(x, W_embed, qkv, MROWS, NQKV, D_);
    // 2) attention -> att [B,S,1024]
    attn_kernel<<<dim3(S_ / 64, H_, B_), 128, 65536>>>(qkv, att);
    // 3) y = att @ W_out    [4096 x 1024 x 1024]
    sgemm64<<<dim3(D_ / 64, MROWS / 64), 256>>>(att, W_out, y, MROWS, D_, D_);
    // 4) out = LN(x + y)
    ln_kernel<<<MROWS, 256>>>(x, y, gamma, beta, out);
}

// round 3
// speedup vs baseline: 1.2408x; 1.2408x over previous
#include <cuda_runtime.h>
#include <cuda_bf16.h>
#include <mma.h>
#include <cstdint>
#include <math.h>

using namespace nvcuda;

#define B_    2
#define S_    2048
#define D_    1024
#define H_    16
#define QKV_  192
#define NQKV  (H_ * QKV_)   /* 3072 */
#define MROWS (B_ * S_)     /* 4096 */

// ---------------- scratch (__device__ globals; no allocation allowed) -------
__device__ float g_qkv[(size_t)MROWS * NQKV];
__device__ float g_att[(size_t)MROWS * D_];
__device__ float g_y[(size_t)MROWS * D_];
__device__ __nv_bfloat16 g_xhi[(size_t)MROWS * D_];
__device__ __nv_bfloat16 g_xlo[(size_t)MROWS * D_];
__device__ __nv_bfloat16 g_wehi[(size_t)NQKV * D_];   // [N=3072][K=1024] K-major
__device__ __nv_bfloat16 g_welo[(size_t)NQKV * D_];
__device__ __nv_bfloat16 g_wohi[(size_t)D_ * D_];     // [N=1024][K=1024]
__device__ __nv_bfloat16 g_wolo[(size_t)D_ * D_];
__device__ __nv_bfloat16 g_ahi[(size_t)MROWS * D_];
__device__ __nv_bfloat16 g_alo[(size_t)MROWS * D_];

// ---------------------------------------------------------------------------
// HMMA (wmma) GEMM: C[M,N] = (Ahi+Alo)[M,K] @ (Bhi+Blo)^T, B stored [N][K].
// 128x128 block tile, 256 threads (8 warps, each 32x64), BK=32,
// 3 accumulating products: hi*hi + hi*lo + lo*hi.
// ---------------------------------------------------------------------------
#define BM 128
#define BN 128
#define BK 32
#define LDS_PAD 40   // smem leading dim (elements): stride 20 banks -> conflict-free

__global__ void __launch_bounds__(256) gemm_wmma(
    const __nv_bfloat16* __restrict__ Ahi, const __nv_bfloat16* __restrict__ Alo,
    const __nv_bfloat16* __restrict__ Bhi, const __nv_bfloat16* __restrict__ Blo,
    float* __restrict__ C, int M, int N, int K)
{
    __shared__ __align__(16) __nv_bfloat16 sAh[BM][LDS_PAD];
    __shared__ __align__(16) __nv_bfloat16 sAl[BM][LDS_PAD];
    __shared__ __align__(16) __nv_bfloat16 sBh[BN][LDS_PAD];
    __shared__ __align__(16) __nv_bfloat16 sBl[BN][LDS_PAD];

    const int tid = threadIdx.x;
    const int wid = tid >> 5;
    const int wm = wid & 3;     // 4 warps along M, 32 rows each
    const int wn = wid >> 2;    // 2 warps along N, 64 cols each
    const int m0 = blockIdx.y * BM;
    const int n0 = blockIdx.x * BN;

    wmma::fragment<wmma::accumulator, 16, 16, 16, float> acc[2][4];
#pragma unroll
    for (int i = 0; i < 2; i++)
#pragma unroll
        for (int j = 0; j < 4; j++) wmma::fill_fragment(acc[i][j], 0.0f);

    // tile loader indices: 512 uint4 per matrix (128 rows x 4 uint4)
    const int lr = tid >> 1;             // 0..127 row
    const int lc = (tid & 1) * 16;       // 0 or 16 (elements), 2 uint4 halves
    for (int k0 = 0; k0 < K; k0 += BK) {
        __syncthreads();
        {
            const size_t ga = (size_t)(m0 + lr) * K + k0 + lc;
            const size_t gb = (size_t)(n0 + lr) * K + k0 + lc;
            *(uint4*)&sAh[lr][lc]      = *(const uint4*)&Ahi[ga];
            *(uint4*)&sAh[lr][lc + 8]  = *(const uint4*)&Ahi[ga + 8];
            *(uint4*)&sAl[lr][lc]      = *(const uint4*)&Alo[ga];
            *(uint4*)&sAl[lr][lc + 8]  = *(const uint4*)&Alo[ga + 8];
            *(uint4*)&sBh[lr][lc]      = *(const uint4*)&Bhi[gb];
            *(uint4*)&sBh[lr][lc + 8]  = *(const uint4*)&Bhi[gb + 8];
            *(uint4*)&sBl[lr][lc]      = *(const uint4*)&Blo[gb];
            *(uint4*)&sBl[lr][lc + 8]  = *(const uint4*)&Blo[gb + 8];
        }
        __syncthreads();

#pragma unroll
        for (int kk = 0; kk < BK; kk += 16) {
            wmma::fragment<wmma::matrix_b, 16, 16, 16, __nv_bfloat16, wmma::col_major> bh[4], bl[4];
#pragma unroll
            for (int j = 0; j < 4; j++) {
                wmma::load_matrix_sync(bh[j], &sBh[wn * 64 + j * 16][kk], LDS_PAD);
                wmma::load_matrix_sync(bl[j], &sBl[wn * 64 + j * 16][kk], LDS_PAD);
            }
#pragma unroll
            for (int i = 0; i < 2; i++) {
                wmma::fragment<wmma::matrix_a, 16, 16, 16, __nv_bfloat16, wmma::row_major> ah, al;
                wmma::load_matrix_sync(ah, &sAh[wm * 32 + i * 16][kk], LDS_PAD);
                wmma::load_matrix_sync(al, &sAl[wm * 32 + i * 16][kk], LDS_PAD);
#pragma unroll
                for (int j = 0; j < 4; j++) {
                    wmma::mma_sync(acc[i][j], ah, bh[j], acc[i][j]);
                    wmma::mma_sync(acc[i][j], ah, bl[j], acc[i][j]);
                    wmma::mma_sync(acc[i][j], al, bh[j], acc[i][j]);
                }
            }
        }
    }

#pragma unroll
    for (int i = 0; i < 2; i++)
#pragma unroll
        for (int j = 0; j < 4; j++)
            wmma::store_matrix_sync(
                &C[(size_t)(m0 + wm * 32 + i * 16) * N + n0 + wn * 64 + j * 16],
                acc[i][j], N, wmma::mem_row_major);
}

// ---------------------------------------------------------------------------
// f32 -> bf16 hi/lo split (vectorized by 4)
// ---------------------------------------------------------------------------
__global__ void __launch_bounds__(256) split4(const float4* __restrict__ in,
                                              __nv_bfloat162* __restrict__ hi,
                                              __nv_bfloat162* __restrict__ lo,
                                              int n4) {
    int i = blockIdx.x * 256 + threadIdx.x;
    if (i >= n4) return;
    float4 v = in[i];
    __nv_bfloat16 h0 = __float2bfloat16(v.x), h1 = __float2bfloat16(v.y);
    __nv_bfloat16 h2 = __float2bfloat16(v.z), h3 = __float2bfloat16(v.w);
    hi[i * 2 + 0] = __nv_bfloat162(h0, h1);
    hi[i * 2 + 1] = __nv_bfloat162(h2, h3);
    lo[i * 2 + 0] = __nv_bfloat162(__float2bfloat16(v.x - __bfloat162float(h0)),
                                   __float2bfloat16(v.y - __bfloat162float(h1)));
    lo[i * 2 + 1] = __nv_bfloat162(__float2bfloat16(v.z - __bfloat162float(h2)),
                                   __float2bfloat16(v.w - __bfloat162float(h3)));
}

// ---------------------------------------------------------------------------
// W[K,N] f32 -> hi/lo [N,K] bf16 (tiled transpose)
// ---------------------------------------------------------------------------
__global__ void __launch_bounds__(256) transpose_split(const float* __restrict__ W,
                                                       __nv_bfloat16* __restrict__ hi,
                                                       __nv_bfloat16* __restrict__ lo,
                                                       int K, int N) {
    __shared__ float t[32][33];
    const int n0 = blockIdx.x * 32, k0 = blockIdx.y * 32;
    const int x = threadIdx.x, y = threadIdx.y;   // 32x8
#pragma unroll
    for (int i = 0; i < 32; i += 8)
        t[y + i][x] = W[(size_t)(k0 + y + i) * N + n0 + x];
    __syncthreads();
#pragma unroll
    for (int i = 0; i < 32; i += 8) {
        float v = t[x][y + i];
        __nv_bfloat16 h = __float2bfloat16(v);
        size_t o = (size_t)(n0 + y + i) * K + k0 + x;
        hi[o] = h;
        lo[o] = __float2bfloat16(v - __bfloat162float(h));
    }
}

// ---------------------------------------------------------------------------
// Attention (fp32 flash kernel, unchanged from R1 — HMMA port is next round)
// ---------------------------------------------------------------------------
__global__ void __launch_bounds__(128) attn_kernel(const float* __restrict__ qkv,
                                                   float* __restrict__ att) {
    extern __shared__ __align__(16) float sm[];
    float* Qs = sm;
    float* Ks = sm + 4096;
    float* Vs = sm + 8192;
    float* Ps = sm + 12288;

    const int tid = threadIdx.x, lane = tid & 31, warp = tid >> 5;
    const int row_t = lane >> 3, col_t = lane & 7;
    const int r_base = warp * 16 + row_t * 4;
    const int c_base = col_t * 8;

    const int q0 = blockIdx.x * 64, h = blockIdx.y, b = blockIdx.z;
    const size_t base = (size_t)b * S_ * NQKV + (size_t)h * QKV_;
    const float scale = 0.125f;

    for (int i = tid; i < 1024; i += 128) {
        int q = i >> 4, dc = (i & 15) << 2;
        float4 v = *(const float4*)&qkv[base + (size_t)(q0 + q) * NQKV + dc];
        Qs[(dc + 0) * 64 + q] = v.x; Qs[(dc + 1) * 64 + q] = v.y;
        Qs[(dc + 2) * 64 + q] = v.z; Qs[(dc + 3) * 64 + q] = v.w;
    }

    float m[4], l[4], o[4][8];
#pragma unroll
    for (int r = 0; r < 4; r++) {
        m[r] = -1e30f; l[r] = 0.0f;
#pragma unroll
        for (int c = 0; c < 8; c++) o[r][c] = 0.0f;
    }

    for (int kt = 0; kt < S_ / 64; kt++) {
        const int k0 = kt * 64;
        const bool fully_masked = (k0 > q0 + 63);
        __syncthreads();
        for (int i = tid; i < 1024; i += 128) {
            int kr = i >> 4, dc = (i & 15) << 2;
            const float* rowp = &qkv[base + (size_t)(k0 + kr) * NQKV];
            *(float4*)&Vs[kr * 64 + dc] = *(const float4*)&rowp[128 + dc];
            if (!fully_masked) {
                float4 kv = *(const float4*)&rowp[64 + dc];
                Ks[(dc + 0) * 64 + kr] = kv.x; Ks[(dc + 1) * 64 + kr] = kv.y;
                Ks[(dc + 2) * 64 + kr] = kv.z; Ks[(dc + 3) * 64 + kr] = kv.w;
            }
        }
        __syncthreads();

        if (!fully_masked) {
            float s[4][8] = {};
#pragma unroll 4
            for (int d = 0; d < 64; d++) {
                float4 a  = *(const float4*)&Qs[d * 64 + r_base];
                float4 b0 = *(const float4*)&Ks[d * 64 + c_base];
                float4 b1 = *(const float4*)&Ks[d * 64 + c_base + 4];
                float ar[4] = {a.x, a.y, a.z, a.w};
                float br[8] = {b0.x, b0.y, b0.z, b0.w, b1.x, b1.y, b1.z, b1.w};
#pragma unroll
                for (int r = 0; r < 4; r++)
#pragma unroll
                    for (int c = 0; c < 8; c++) s[r][c] += ar[r] * br[c];
            }
#pragma unroll
            for (int r = 0; r < 4; r++) {
                int gq = q0 + r_base + r;
#pragma unroll
                for (int c = 0; c < 8; c++) {
                    int gk = k0 + c_base + c;
                    s[r][c] = (gk <= gq) ? s[r][c] * scale : 0.0f;
                }
            }
#pragma unroll
            for (int r = 0; r < 4; r++) {
                float mt = s[r][0];
#pragma unroll
                for (int c = 1; c < 8; c++) mt = fmaxf(mt, s[r][c]);
                mt = fmaxf(mt, __shfl_xor_sync(0xffffffffu, mt, 1));
                mt = fmaxf(mt, __shfl_xor_sync(0xffffffffu, mt, 2));
                mt = fmaxf(mt, __shfl_xor_sync(0xffffffffu, mt, 4));
                float mn = fmaxf(m[r], mt);
                float alpha = __expf(m[r] - mn);
                m[r] = mn;
                float ls = 0.0f;
#pragma unroll
                for (int c = 0; c < 8; c++) { s[r][c] = __expf(s[r][c] - mn); ls += s[r][c]; }
                l[r] = l[r] * alpha + ls;
#pragma unroll
                for (int c = 0; c < 8; c++) o[r][c] *= alpha;
            }
#pragma unroll
            for (int c = 0; c < 8; c++) {
                *(float4*)&Ps[(c_base + c) * 64 + r_base] =
                    make_float4(s[0][c], s[1][c], s[2][c], s[3][c]);
            }
            __syncthreads();
#pragma unroll 4
            for (int kk = 0; kk < 64; kk++) {
                float4 pp = *(const float4*)&Ps[kk * 64 + r_base];
                float4 v0 = *(const float4*)&Vs[kk * 64 + c_base];
                float4 v1 = *(const float4*)&Vs[kk * 64 + c_base + 4];
                float pr[4] = {pp.x, pp.y, pp.z, pp.w};
                float vr[8] = {v0.x, v0.y, v0.z, v0.w, v1.x, v1.y, v1.z, v1.w};
#pragma unroll
                for (int r = 0; r < 4; r++)
#pragma unroll
                    for (int c = 0; c < 8; c++) o[r][c] += pr[r] * vr[c];
            }
        } else {
            float vs[8] = {};
#pragma unroll 4
            for (int kk = 0; kk < 64; kk++) {
                float4 v0 = *(const float4*)&Vs[kk * 64 + c_base];
                float4 v1 = *(const float4*)&Vs[kk * 64 + c_base + 4];
                vs[0] += v0.x; vs[1] += v0.y; vs[2] += v0.z; vs[3] += v0.w;
                vs[4] += v1.x; vs[5] += v1.y; vs[6] += v1.z; vs[7] += v1.w;
            }
#pragma unroll
            for (int r = 0; r < 4; r++) {
                float mn = fmaxf(m[r], 0.0f);
                float alpha = __expf(m[r] - mn);
                float e0 = __expf(-mn);
                m[r] = mn;
                l[r] = l[r] * alpha + 8.0f * e0;
#pragma unroll
                for (int c = 0; c < 8; c++) o[r][c] = o[r][c] * alpha + e0 * vs[c];
            }
        }
    }

#pragma unroll
    for (int r = 0; r < 4; r++) {
        float lt = l[r];
        lt += __shfl_xor_sync(0xffffffffu, lt, 1);
        lt += __shfl_xor_sync(0xffffffffu, lt, 2);
        lt += __shfl_xor_sync(0xffffffffu, lt, 4);
        float inv = 1.0f / lt;
        size_t orow = ((size_t)b * S_ + q0 + r_base + r) * D_ + h * 64 + c_base;
        *(float4*)&att[orow] =
            make_float4(o[r][0] * inv, o[r][1] * inv, o[r][2] * inv, o[r][3] * inv);
        *(float4*)&att[orow + 4] =
            make_float4(o[r][4] * inv, o[r][5] * inv, o[r][6] * inv, o[r][7] * inv);
    }
}

// ---------------------------------------------------------------------------
// out = LayerNorm(x + y) (unchanged)
// ---------------------------------------------------------------------------
__global__ void __launch_bounds__(256) ln_kernel(const float* __restrict__ x,
                                                 const float* __restrict__ y,
                                                 const float* __restrict__ gamma,
                                                 const float* __restrict__ beta,
                                                 float* __restrict__ out) {
    __shared__ float red[8];
    const int row = blockIdx.x, t = threadIdx.x;
    const int lane = t & 31, wid = t >> 5;
    const size_t off = (size_t)row * D_;

    float v[4], s = 0.0f;
#pragma unroll
    for (int i = 0; i < 4; i++) {
        int idx = t + i * 256;
        v[i] = x[off + idx] + y[off + idx];
        s += v[i];
    }
    for (int d = 16; d > 0; d >>= 1) s += __shfl_xor_sync(0xffffffffu, s, d);
    if (lane == 0) red[wid] = s;
    __syncthreads();
    float tot = 0.0f;
#pragma unroll
    for (int w = 0; w < 8; w++) tot += red[w];
    const float mean = tot * (1.0f / D_);
    __syncthreads();
    float ss = 0.0f;
#pragma unroll
    for (int i = 0; i < 4; i++) { float d = v[i] - mean; ss += d * d; }
    for (int d = 16; d > 0; d >>= 1) ss += __shfl_xor_sync(0xffffffffu, ss, d);
    if (lane == 0) red[wid] = ss;
    __syncthreads();
    float tot2 = 0.0f;
#pragma unroll
    for (int w = 0; w < 8; w++) tot2 += red[w];
    const float rstd = rsqrtf(tot2 * (1.0f / D_) + 1e-3f);
#pragma unroll
    for (int i = 0; i < 4; i++) {
        int idx = t + i * 256;
        out[off + idx] = (v[i] - mean) * rstd * gamma[idx] + beta[idx];
    }
}

// ---------------------------------------------------------------------------
extern "C" void kernel_launch(void* const* d_in, const int* in_sizes, int n_in,
                              void* d_out, int out_size) {
    const float* x       = (const float*)d_in[0];
    const float* W_embed = (const float*)d_in[2];
    const float* W_out   = (const float*)d_in[3];
    const float* gamma   = (const float*)d_in[4];
    const float* beta    = (const float*)d_in[5];
    float* out = (float*)d_out;

    float *qkv, *att, *y;
    __nv_bfloat16 *xhi, *xlo, *wehi, *welo, *wohi, *wolo, *ahi, *alo;
    cudaGetSymbolAddress((void**)&qkv,  g_qkv);
    cudaGetSymbolAddress((void**)&att,  g_att);
    cudaGetSymbolAddress((void**)&y,    g_y);
    cudaGetSymbolAddress((void**)&xhi,  g_xhi);
    cudaGetSymbolAddress((void**)&xlo,  g_xlo);
    cudaGetSymbolAddress((void**)&wehi, g_wehi);
    cudaGetSymbolAddress((void**)&welo, g_welo);
    cudaGetSymbolAddress((void**)&wohi, g_wohi);
    cudaGetSymbolAddress((void**)&wolo, g_wolo);
    cudaGetSymbolAddress((void**)&ahi,  g_ahi);
    cudaGetSymbolAddress((void**)&alo,  g_alo);

    cudaFuncSetAttribute(attn_kernel, cudaFuncAttributeMaxDynamicSharedMemorySize, 65536);

    // 0) precision-split inputs and transposed weights (bf16 hi/lo)
    split4<<<(MROWS * D_ / 4 + 255) / 256, 256>>>((const float4*)x,
        (__nv_bfloat162*)xhi, (__nv_bfloat162*)xlo, MROWS * D_ / 4);
    transpose_split<<<dim3(NQKV / 32, D_ / 32), dim3(32, 8)>>>(W_embed, wehi, welo, D_, NQKV);
    transpose_split<<<dim3(D_ / 32, D_ / 32), dim3(32, 8)>>>(W_out, wohi, wolo, D_, D_);

    // 1) qkv = x @ W_embed   (HMMA, 3-product bf16 split)
    gemm_wmma<<<dim3(NQKV / BN, MROWS / BM), 256>>>(xhi, xlo, wehi, welo, qkv, MROWS, NQKV, D_);

    // 2) attention
    attn_kernel<<<dim3(S_ / 64, H_, B_), 128, 65536>>>(qkv, att);

    // 3) y = att @ W_out (split att first)
    split4<<<(MROWS * D_ / 4 + 255) / 256, 256>>>((const float4*)att,
        (__nv_bfloat162*)ahi, (__nv_bfloat162*)alo, MROWS * D_ / 4);
    gemm_wmma<<<dim3(D_ / BN, MROWS / BM), 256>>>(ahi, alo, wohi, wolo, y, MROWS, D_, D_);

    // 4) out = LN(x + y)
    ln_kernel<<<MROWS, 256>>>(x, y, gamma, beta, out);
}

// round 7
// speedup vs baseline: 1.7060x; 1.3750x over previous
#include <cuda_runtime.h>
#include <cuda_bf16.h>
#include <mma.h>
#include <cstdint>
#include <math.h>

using namespace nvcuda;

#define B_    2
#define S_    2048
#define D_    1024
#define H_    16
#define QKV_  192
#define NQKV  (H_ * QKV_)   /* 3072 */
#define MROWS (B_ * S_)     /* 4096 */

// ---------------- scratch ---------------------------------------------------
__device__ __nv_bfloat16 g_qkvhi[(size_t)MROWS * NQKV];
__device__ __nv_bfloat16 g_qkvlo[(size_t)MROWS * NQKV];
__device__ __nv_bfloat16 g_xhi[(size_t)MROWS * D_];
__device__ __nv_bfloat16 g_xlo[(size_t)MROWS * D_];
__device__ __nv_bfloat16 g_wehi[(size_t)NQKV * D_];   // [N][K]
__device__ __nv_bfloat16 g_welo[(size_t)NQKV * D_];
__device__ __nv_bfloat16 g_wohi[(size_t)D_ * D_];
__device__ __nv_bfloat16 g_wolo[(size_t)D_ * D_];
__device__ __nv_bfloat16 g_ahi[(size_t)MROWS * D_];
__device__ __nv_bfloat16 g_alo[(size_t)MROWS * D_];
__device__ float g_y[(size_t)MROWS * D_];
__device__ float g_sufv[(size_t)B_ * H_ * 33 * 64];

// ---------------- cp.async helpers -----------------------------------------
__device__ __forceinline__ uint32_t smem_u32(const void* p) {
    uint32_t a;
    asm("{ .reg .u64 t; cvta.to.shared.u64 t, %1; cvt.u32.u64 %0, t; }" : "=r"(a) : "l"(p));
    return a;
}
#define CP_ASYNC16(dst, src) \
    asm volatile("cp.async.cg.shared.global [%0], [%1], 16;" :: "r"(dst), "l"(src))
#define CP_COMMIT() asm volatile("cp.async.commit_group;")
#define CP_WAIT0()  asm volatile("cp.async.wait_group 0;")
#define CP_WAIT1()  asm volatile("cp.async.wait_group 1;")

// ---------------------------------------------------------------------------
// HMMA GEMM: C = (Ahi+Alo)[M,K] @ (Bhi+Blo)^T, B stored [N][K].
// 128x128 tile, 256 thr, BK=32, cp.async double-buffered.
// MODE 0: C fp32. MODE 1: C -> hi/lo bf16 split.
// ---------------------------------------------------------------------------
#define BM 128
#define BN 128
#define BK 32
#define GP 40          // smem pitch (elements)
#define MATB (BM * GP * 2)        // 10240 bytes per matrix
#define STAGEB (4 * MATB)         // 40960 per stage
#define GSMEM (2 * STAGEB)        // 81920

template<int MODE>
__global__ void __launch_bounds__(256) gemm_wmma(
    const __nv_bfloat16* __restrict__ Ahi, const __nv_bfloat16* __restrict__ Alo,
    const __nv_bfloat16* __restrict__ Bhi, const __nv_bfloat16* __restrict__ Blo,
    float* __restrict__ C, __nv_bfloat16* __restrict__ Chi,
    __nv_bfloat16* __restrict__ Clo, int M, int N, int K)
{
    extern __shared__ __align__(16) char smem[];
    const uint32_t sb = smem_u32(smem);
    const int tid = threadIdx.x;
    const int wid = tid >> 5;
    const int wm = wid & 3, wn = wid >> 2;
    const int m0 = blockIdx.y * BM, n0 = blockIdx.x * BN;

    wmma::fragment<wmma::accumulator, 16, 16, 16, float> acc[2][4];
#pragma unroll
    for (int i = 0; i < 2; i++)
#pragma unroll
        for (int j = 0; j < 4; j++) wmma::fill_fragment(acc[i][j], 0.0f);

    // loader: 512 uint4 per matrix; thread covers uint4s u0 and u0+1 (consecutive)
    const int u0 = tid * 2;
    const int lrow = u0 >> 2;              // 0..127
    const int lcb = (u0 & 3) * 16;         // byte col: 0 or 32
    const char* gAh = (const char*)&Ahi[(size_t)(m0 + lrow) * K] + lcb;
    const char* gAl = (const char*)&Alo[(size_t)(m0 + lrow) * K] + lcb;
    const char* gBh = (const char*)&Bhi[(size_t)(n0 + lrow) * K] + lcb;
    const char* gBl = (const char*)&Blo[(size_t)(n0 + lrow) * K] + lcb;
    const uint32_t soff = lrow * (GP * 2) + lcb;

    const int KT = K / BK;
    auto issue = [&](int st, int kt) {
        const uint32_t base = sb + st * STAGEB + soff;
        const size_t gk = (size_t)kt * (BK * 2);
        CP_ASYNC16(base,            gAh + gk);  CP_ASYNC16(base + 16,            gAh + gk + 16);
        CP_ASYNC16(base + MATB,     gAl + gk);  CP_ASYNC16(base + MATB + 16,     gAl + gk + 16);
        CP_ASYNC16(base + 2*MATB,   gBh + gk);  CP_ASYNC16(base + 2*MATB + 16,   gBh + gk + 16);
        CP_ASYNC16(base + 3*MATB,   gBl + gk);  CP_ASYNC16(base + 3*MATB + 16,   gBl + gk + 16);
    };

    issue(0, 0);
    CP_COMMIT();

    for (int kt = 0; kt < KT; kt++) {
        if (kt + 1 < KT) { issue((kt + 1) & 1, kt + 1); CP_COMMIT(); CP_WAIT1(); }
        else             { CP_WAIT0(); }
        __syncthreads();

        const __nv_bfloat16* sAh = (const __nv_bfloat16*)(smem + (kt & 1) * STAGEB);
        const __nv_bfloat16* sAl = sAh + BM * GP;
        const __nv_bfloat16* sBh = sAl + BM * GP;
        const __nv_bfloat16* sBl = sBh + BM * GP;

#pragma unroll
        for (int kk = 0; kk < BK; kk += 16) {
            wmma::fragment<wmma::matrix_b, 16, 16, 16, __nv_bfloat16, wmma::col_major> bh[4], bl[4];
#pragma unroll
            for (int j = 0; j < 4; j++) {
                wmma::load_matrix_sync(bh[j], sBh + (wn * 64 + j * 16) * GP + kk, GP);
                wmma::load_matrix_sync(bl[j], sBl + (wn * 64 + j * 16) * GP + kk, GP);
            }
#pragma unroll
            for (int i = 0; i < 2; i++) {
                wmma::fragment<wmma::matrix_a, 16, 16, 16, __nv_bfloat16, wmma::row_major> ah, al;
                wmma::load_matrix_sync(ah, sAh + (wm * 32 + i * 16) * GP + kk, GP);
                wmma::load_matrix_sync(al, sAl + (wm * 32 + i * 16) * GP + kk, GP);
#pragma unroll
                for (int j = 0; j < 4; j++) {
                    wmma::mma_sync(acc[i][j], ah, bh[j], acc[i][j]);
                    wmma::mma_sync(acc[i][j], ah, bl[j], acc[i][j]);
                    wmma::mma_sync(acc[i][j], al, bh[j], acc[i][j]);
                }
            }
        }
        __syncthreads();
    }

    if (MODE == 0) {
#pragma unroll
        for (int i = 0; i < 2; i++)
#pragma unroll
            for (int j = 0; j < 4; j++)
                wmma::store_matrix_sync(
                    &C[(size_t)(m0 + wm * 32 + i * 16) * N + n0 + wn * 64 + j * 16],
                    acc[i][j], N, wmma::mem_row_major);
    } else {
        float* stage = (float*)smem;   // 128x128 fp32 = 64KB
#pragma unroll
        for (int i = 0; i < 2; i++)
#pragma unroll
            for (int j = 0; j < 4; j++)
                wmma::store_matrix_sync(
                    &stage[(size_t)(wm * 32 + i * 16) * BN + wn * 64 + j * 16],
                    acc[i][j], BN, wmma::mem_row_major);
        __syncthreads();
#pragma unroll
        for (int it = 0; it < 16; it++) {
            const int fi = tid + it * 256;
            const int row = fi >> 5, c4 = (fi & 31) * 4;
            float4 v = *(const float4*)&stage[row * BN + c4];
            __nv_bfloat16 h0 = __float2bfloat16(v.x), h1 = __float2bfloat16(v.y);
            __nv_bfloat16 h2 = __float2bfloat16(v.z), h3 = __float2bfloat16(v.w);
            __nv_bfloat162 hA(h0, h1), hB(h2, h3);
            __nv_bfloat162 lA(__float2bfloat16(v.x - __bfloat162float(h0)),
                              __float2bfloat16(v.y - __bfloat162float(h1)));
            __nv_bfloat162 lB(__float2bfloat16(v.z - __bfloat162float(h2)),
                              __float2bfloat16(v.w - __bfloat162float(h3)));
            const size_t o = (size_t)(m0 + row) * N + n0 + c4;
            *(__nv_bfloat162*)&Chi[o] = hA; *(__nv_bfloat162*)&Chi[o + 2] = hB;
            *(__nv_bfloat162*)&Clo[o] = lA; *(__nv_bfloat162*)&Clo[o + 2] = lB;
        }
    }
}

// ---------------------------------------------------------------------------
// f32 -> bf16 hi/lo split
// ---------------------------------------------------------------------------
__global__ void __launch_bounds__(256) split4(const float4* __restrict__ in,
                                              __nv_bfloat162* __restrict__ hi,
                                              __nv_bfloat162* __restrict__ lo,
                                              int n4) {
    int i = blockIdx.x * 256 + threadIdx.x;
    if (i >= n4) return;
    float4 v = in[i];
    __nv_bfloat16 h0 = __float2bfloat16(v.x), h1 = __float2bfloat16(v.y);
    __nv_bfloat16 h2 = __float2bfloat16(v.z), h3 = __float2bfloat16(v.w);
    hi[i * 2 + 0] = __nv_bfloat162(h0, h1);
    hi[i * 2 + 1] = __nv_bfloat162(h2, h3);
    lo[i * 2 + 0] = __nv_bfloat162(__float2bfloat16(v.x - __bfloat162float(h0)),
                                   __float2bfloat16(v.y - __bfloat162float(h1)));
    lo[i * 2 + 1] = __nv_bfloat162(__float2bfloat16(v.z - __bfloat162float(h2)),
                                   __float2bfloat16(v.w - __bfloat162float(h3)));
}

// ---------------------------------------------------------------------------
// W[K,N] f32 -> hi/lo [N,K]
// ---------------------------------------------------------------------------
__global__ void __launch_bounds__(256) transpose_split(const float* __restrict__ W,
                                                       __nv_bfloat16* __restrict__ hi,
                                                       __nv_bfloat16* __restrict__ lo,
                                                       int K, int N) {
    __shared__ float t[32][33];
    const int n0 = blockIdx.x * 32, k0 = blockIdx.y * 32;
    const int x = threadIdx.x, y = threadIdx.y;
#pragma unroll
    for (int i = 0; i < 32; i += 8)
        t[y + i][x] = W[(size_t)(k0 + y + i) * N + n0 + x];
    __syncthreads();
#pragma unroll
    for (int i = 0; i < 32; i += 8) {
        float v = t[x][y + i];
        __nv_bfloat16 h = __float2bfloat16(v);
        size_t o = (size_t)(n0 + y + i) * K + k0 + x;
        hi[o] = h;
        lo[o] = __float2bfloat16(v - __bfloat162float(h));
    }
}

// ---------------------------------------------------------------------------
// suffix colsum of V per (b,h): sufv[b][h][t][d] = sum over keys k >= 64t
// ---------------------------------------------------------------------------
__global__ void __launch_bounds__(64) suffixv(const __nv_bfloat16* __restrict__ qhi,
                                              const __nv_bfloat16* __restrict__ qlo,
                                              float* __restrict__ sufv) {
    const int h = blockIdx.x, b = blockIdx.y, d = threadIdx.x;
    float acc = 0.0f;
    float* base = &sufv[((size_t)(b * H_ + h) * 33) * 64 + d];
    base[32 * 64] = 0.0f;
    const size_t col = (size_t)h * QKV_ + 128 + d;
    for (int t = 31; t >= 0; t--) {
#pragma unroll 4
        for (int kk = 63; kk >= 0; kk--) {
            const size_t o = (size_t)(b * S_ + t * 64 + kk) * NQKV + col;
            acc += __bfloat162float(qhi[o]) + __bfloat162float(qlo[o]);
        }
        base[t * 64] = acc;
    }
}

// ---------------------------------------------------------------------------
// wmma flash attention. Q tile 128 rows, K tile 64 keys.
// Key loop covers 64-key tiles 0 .. 2*qt+1  (keys [0, 128*(qt+1)));
// remaining keys handled analytically via suffix colsum (logit==0 each).
// ---------------------------------------------------------------------------
#define AP 72          // bf16 pitch
#define SFP 68         // fp32 pitch
#define OFF_QH 0
#define OFF_QL (OFF_QH + 128 * AP * 2)
#define OFF_KH (OFF_QL + 128 * AP * 2)
#define OFF_KL (OFF_KH + 64 * AP * 2)
#define OFF_VH (OFF_KL + 64 * AP * 2)
#define OFF_VL (OFF_VH + 64 * AP * 2)
#define OFF_PH (OFF_VL + 64 * AP * 2)
#define OFF_PL (OFF_PH + 128 * AP * 2)
#define OFF_SF (OFF_PL + 128 * AP * 2)
#define OFF_O  (OFF_SF + 128 * SFP * 4)
#define ASMEM  (OFF_O + 128 * 64 * 4)

__global__ void __launch_bounds__(256) attn_wmma(
    const __nv_bfloat16* __restrict__ qkvhi, const __nv_bfloat16* __restrict__ qkvlo,
    const float* __restrict__ sufv,
    __nv_bfloat16* __restrict__ ahi, __nv_bfloat16* __restrict__ alo)
{
    extern __shared__ __align__(16) char smem[];
    __nv_bfloat16* sQh = (__nv_bfloat16*)(smem + OFF_QH);
    __nv_bfloat16* sQl = (__nv_bfloat16*)(smem + OFF_QL);
    __nv_bfloat16* sKh = (__nv_bfloat16*)(smem + OFF_KH);
    __nv_bfloat16* sKl = (__nv_bfloat16*)(smem + OFF_KL);
    __nv_bfloat16* sVh = (__nv_bfloat16*)(smem + OFF_VH);
    __nv_bfloat16* sVl = (__nv_bfloat16*)(smem + OFF_VL);
    __nv_bfloat16* sPh = (__nv_bfloat16*)(smem + OFF_PH);
    __nv_bfloat16* sPl = (__nv_bfloat16*)(smem + OFF_PL);
    float* sSF = (float*)(smem + OFF_SF);
    float* sO  = (float*)(smem + OFF_O);

    const int tid = threadIdx.x, wid = tid >> 5;
    const int qt = blockIdx.x, h = blockIdx.y, b = blockIdx.z;
    const int q0 = qt * 128;
    const size_t base = (size_t)b * S_ * NQKV + (size_t)h * QKV_;

    // load Q hi/lo (128 x 64)
#pragma unroll
    for (int j = 0; j < 4; j++) {
        const int i = tid + j * 256;
        const int row = i >> 3, c8 = (i & 7) * 8;
        const size_t g = base + (size_t)(q0 + row) * NQKV + c8;
        *(uint4*)&sQh[row * AP + c8] = *(const uint4*)&qkvhi[g];
        *(uint4*)&sQl[row * AP + c8] = *(const uint4*)&qkvlo[g];
    }
    // zero O
#pragma unroll
    for (int j = 0; j < 8; j++)
        *(float4*)&sO[(tid + j * 256) * 4] = make_float4(0.f, 0.f, 0.f, 0.f);

    const int srow = tid >> 1;                // softmax row owned by this thread
    const int scb  = (tid & 1) * 32;          // 32-col half
    float m = -1e30f, l = 0.0f, alpha = 0.0f;
    const float scale = 0.125f;
    const int gq = q0 + srow;

    const int KTILES = 2 * qt + 2;            // keys [0, 128*(qt+1))
    for (int kt = 0; kt < KTILES; kt++) {
        const int k0 = kt * 64;
        __syncthreads();
        // load K,V hi/lo (64 x 64 each)
#pragma unroll
        for (int j = 0; j < 2; j++) {
            const int i = tid + j * 256;
            const int row = i >> 3, c8 = (i & 7) * 8;
            const size_t g = base + (size_t)(k0 + row) * NQKV + c8;
            *(uint4*)&sKh[row * AP + c8] = *(const uint4*)&qkvhi[g + 64];
            *(uint4*)&sKl[row * AP + c8] = *(const uint4*)&qkvlo[g + 64];
            *(uint4*)&sVh[row * AP + c8] = *(const uint4*)&qkvhi[g + 128];
            *(uint4*)&sVl[row * AP + c8] = *(const uint4*)&qkvlo[g + 128];
        }
        __syncthreads();

        // S = Q @ K^T  (warp: 16 rows x 64 keys)
        {
            wmma::fragment<wmma::accumulator, 16, 16, 16, float> sacc[4];
#pragma unroll
            for (int j = 0; j < 4; j++) wmma::fill_fragment(sacc[j], 0.0f);
#pragma unroll
            for (int ks = 0; ks < 4; ks++) {
                const int kk = ks * 16;
                wmma::fragment<wmma::matrix_a, 16, 16, 16, __nv_bfloat16, wmma::row_major> ah, al;
                wmma::load_matrix_sync(ah, sQh + (wid * 16) * AP + kk, AP);
                wmma::load_matrix_sync(al, sQl + (wid * 16) * AP + kk, AP);
#pragma unroll
                for (int j = 0; j < 4; j++) {
                    wmma::fragment<wmma::matrix_b, 16, 16, 16, __nv_bfloat16, wmma::col_major> bh, bl;
                    wmma::load_matrix_sync(bh, sKh + (j * 16) * AP + kk, AP);
                    wmma::load_matrix_sync(bl, sKl + (j * 16) * AP + kk, AP);
                    wmma::mma_sync(sacc[j], ah, bh, sacc[j]);
                    wmma::mma_sync(sacc[j], ah, bl, sacc[j]);
                    wmma::mma_sync(sacc[j], al, bh, sacc[j]);
                }
            }
#pragma unroll
            for (int j = 0; j < 4; j++)
                wmma::store_matrix_sync(&sSF[(wid * 16) * SFP + j * 16], sacc[j],
                                        SFP, wmma::mem_row_major);
        }
        __syncthreads();

        // mask + online softmax; write P hi/lo
        {
            float s[32];
#pragma unroll
            for (int c4 = 0; c4 < 8; c4++) {
                float4 v = *(const float4*)&sSF[srow * SFP + scb + c4 * 4];
                s[c4 * 4 + 0] = v.x; s[c4 * 4 + 1] = v.y;
                s[c4 * 4 + 2] = v.z; s[c4 * 4 + 3] = v.w;
            }
            const int lim = gq - k0;   // keys with (k0+c) <= gq stay
#pragma unroll
            for (int c = 0; c < 32; c++) {
                float sv = s[c] * scale;
                if (scb + c > lim) sv = 0.0f;   // multiplicative mask -> logit 0
                s[c] = sv;
            }
            float tmax = s[0];
#pragma unroll
            for (int c = 1; c < 32; c++) tmax = fmaxf(tmax, s[c]);
            tmax = fmaxf(tmax, __shfl_xor_sync(0xffffffffu, tmax, 1));
            const float mn = fmaxf(m, tmax);
            alpha = __expf(m - mn);
            m = mn;
            float ps = 0.0f;
#pragma unroll
            for (int c = 0; c < 32; c++) { s[c] = __expf(s[c] - mn); ps += s[c]; }
            ps += __shfl_xor_sync(0xffffffffu, ps, 1);
            l = l * alpha + ps;
#pragma unroll
            for (int c4 = 0; c4 < 4; c4++) {
                __nv_bfloat16 hh[8], ll[8];
#pragma unroll
                for (int e = 0; e < 8; e++) {
                    const float p = s[c4 * 8 + e];
                    hh[e] = __float2bfloat16(p);
                    ll[e] = __float2bfloat16(p - __bfloat162float(hh[e]));
                }
                *(uint4*)&sPh[srow * AP + scb + c4 * 8] = *(const uint4*)hh;
                *(uint4*)&sPl[srow * AP + scb + c4 * 8] = *(const uint4*)ll;
            }
        }
        __syncthreads();

        // PV = P @ V  (warp: 16 rows x 64 dims)
        {
            wmma::fragment<wmma::accumulator, 16, 16, 16, float> pacc[4];
#pragma unroll
            for (int j = 0; j < 4; j++) wmma::fill_fragment(pacc[j], 0.0f);
#pragma unroll
            for (int ks = 0; ks < 4; ks++) {
                const int kk = ks * 16;
                wmma::fragment<wmma::matrix_a, 16, 16, 16, __nv_bfloat16, wmma::row_major> ah, al;
                wmma::load_matrix_sync(ah, sPh + (wid * 16) * AP + kk, AP);
                wmma::load_matrix_sync(al, sPl + (wid * 16) * AP + kk, AP);
#pragma unroll
                for (int j = 0; j < 4; j++) {
                    wmma::fragment<wmma::matrix_b, 16, 16, 16, __nv_bfloat16, wmma::row_major> bh, bl;
                    wmma::load_matrix_sync(bh, sVh + kk * AP + j * 16, AP);
                    wmma::load_matrix_sync(bl, sVl + kk * AP + j * 16, AP);
                    wmma::mma_sync(pacc[j], ah, bh, pacc[j]);
                    wmma::mma_sync(pacc[j], ah, bl, pacc[j]);
                    wmma::mma_sync(pacc[j], al, bh, pacc[j]);
                }
            }
#pragma unroll
            for (int j = 0; j < 4; j++)
                wmma::store_matrix_sync(&sSF[(wid * 16) * SFP + j * 16], pacc[j],
                                        SFP, wmma::mem_row_major);
        }
        __syncthreads();

        // O = O*alpha + PV
#pragma unroll
        for (int c4 = 0; c4 < 8; c4++) {
            float4 o = *(const float4*)&sO[srow * 64 + scb + c4 * 4];
            float4 p = *(const float4*)&sSF[srow * SFP + scb + c4 * 4];
            o.x = o.x * alpha + p.x; o.y = o.y * alpha + p.y;
            o.z = o.z * alpha + p.z; o.w = o.w * alpha + p.w;
            *(float4*)&sO[srow * 64 + scb + c4 * 4] = o;
        }
    }

    // suffix: keys >= 128*(qt+1), all masked -> logit 0 each
    const int cnt = S_ - 128 * (qt + 1);
    float ofin[32];
#pragma unroll
    for (int c4 = 0; c4 < 8; c4++) {
        float4 o = *(const float4*)&sO[srow * 64 + scb + c4 * 4];
        ofin[c4 * 4 + 0] = o.x; ofin[c4 * 4 + 1] = o.y;
        ofin[c4 * 4 + 2] = o.z; ofin[c4 * 4 + 3] = o.w;
    }
    if (cnt > 0) {
        const float mn = fmaxf(m, 0.0f);
        const float a2 = __expf(m - mn);
        const float e0 = __expf(-mn);
        l = l * a2 + (float)cnt * e0;
        const float* sv = &sufv[((size_t)(b * H_ + h) * 33 + 2 * (qt + 1)) * 64 + scb];
#pragma unroll
        for (int c = 0; c < 32; c++) ofin[c] = ofin[c] * a2 + e0 * sv[c];
    }
    const float inv = 1.0f / l;
    const size_t orow = (size_t)(b * S_ + q0 + srow) * D_ + h * 64 + scb;
#pragma unroll
    for (int c4 = 0; c4 < 4; c4++) {
        __nv_bfloat16 hh[8], ll[8];
#pragma unroll
        for (int e = 0; e < 8; e++) {
            const float v = ofin[c4 * 8 + e] * inv;
            hh[e] = __float2bfloat16(v);
            ll[e] = __float2bfloat16(v - __bfloat162float(hh[e]));
        }
        *(uint4*)&ahi[orow + c4 * 8] = *(const uint4*)hh;
        *(uint4*)&alo[orow + c4 * 8] = *(const uint4*)ll;
    }
}

// ---------------------------------------------------------------------------
// out = LayerNorm(x + y)
// ---------------------------------------------------------------------------
__global__ void __launch_bounds__(256) ln_kernel(const float* __restrict__ x,
                                                 const float* __restrict__ y,
                                                 const float* __restrict__ gamma,
                                                 const float* __restrict__ beta,
                                                 float* __restrict__ out) {
    __shared__ float red[8];
    const int row = blockIdx.x, t = threadIdx.x;
    const int lane = t & 31, wid = t >> 5;
    const size_t off = (size_t)row * D_;

    float v[4], s = 0.0f;
#pragma unroll
    for (int i = 0; i < 4; i++) {
        int idx = t + i * 256;
        v[i] = x[off + idx] + y[off + idx];
        s += v[i];
    }
    for (int d = 16; d > 0; d >>= 1) s += __shfl_xor_sync(0xffffffffu, s, d);
    if (lane == 0) red[wid] = s;
    __syncthreads();
    float tot = 0.0f;
#pragma unroll
    for (int w = 0; w < 8; w++) tot += red[w];
    const float mean = tot * (1.0f / D_);
    __syncthreads();
    float ss = 0.0f;
#pragma unroll
    for (int i = 0; i < 4; i++) { float d = v[i] - mean; ss += d * d; }
    for (int d = 16; d > 0; d >>= 1) ss += __shfl_xor_sync(0xffffffffu, ss, d);
    if (lane == 0) red[wid] = ss;
    __syncthreads();
    float tot2 = 0.0f;
#pragma unroll
    for (int w = 0; w < 8; w++) tot2 += red[w];
    const float rstd = rsqrtf(tot2 * (1.0f / D_) + 1e-3f);
#pragma unroll
    for (int i = 0; i < 4; i++) {
        int idx = t + i * 256;
        out[off + idx] = (v[i] - mean) * rstd * gamma[idx] + beta[idx];
    }
}

// ---------------------------------------------------------------------------
extern "C" void kernel_launch(void* const* d_in, const int* in_sizes, int n_in,
                              void* d_out, int out_size) {
    const float* x       = (const float*)d_in[0];
    const float* W_embed = (const float*)d_in[2];
    const float* W_out   = (const float*)d_in[3];
    const float* gamma   = (const float*)d_in[4];
    const float* beta    = (const float*)d_in[5];
    float* out = (float*)d_out;

    __nv_bfloat16 *qhi, *qlo, *xhi, *xlo, *wehi, *welo, *wohi, *wolo, *ahi, *alo;
    float *y, *sufv;
    cudaGetSymbolAddress((void**)&qhi,  g_qkvhi);
    cudaGetSymbolAddress((void**)&qlo,  g_qkvlo);
    cudaGetSymbolAddress((void**)&xhi,  g_xhi);
    cudaGetSymbolAddress((void**)&xlo,  g_xlo);
    cudaGetSymbolAddress((void**)&wehi, g_wehi);
    cudaGetSymbolAddress((void**)&welo, g_welo);
    cudaGetSymbolAddress((void**)&wohi, g_wohi);
    cudaGetSymbolAddress((void**)&wolo, g_wolo);
    cudaGetSymbolAddress((void**)&ahi,  g_ahi);
    cudaGetSymbolAddress((void**)&alo,  g_alo);
    cudaGetSymbolAddress((void**)&y,    g_y);
    cudaGetSymbolAddress((void**)&sufv, g_sufv);

    cudaFuncSetAttribute(gemm_wmma<0>, cudaFuncAttributeMaxDynamicSharedMemorySize, GSMEM);
    cudaFuncSetAttribute(gemm_wmma<1>, cudaFuncAttributeMaxDynamicSharedMemorySize, GSMEM);
    cudaFuncSetAttribute(attn_wmma, cudaFuncAttributeMaxDynamicSharedMemorySize, ASMEM);

    // 0) splits / transposes
    split4<<<(MROWS * D_ / 4 + 255) / 256, 256>>>((const float4*)x,
        (__nv_bfloat162*)xhi, (__nv_bfloat162*)xlo, MROWS * D_ / 4);
    transpose_split<<<dim3(NQKV / 32, D_ / 32), dim3(32, 8)>>>(W_embed, wehi, welo, D_, NQKV);
    transpose_split<<<dim3(D_ / 32, D_ / 32), dim3(32, 8)>>>(W_out, wohi, wolo, D_, D_);

    // 1) qkv = x @ W_embed -> bf16 hi/lo directly
    gemm_wmma<1><<<dim3(NQKV / BN, MROWS / BM), 256, GSMEM>>>(
        xhi, xlo, wehi, welo, nullptr, qhi, qlo, MROWS, NQKV, D_);

    // 1b) suffix colsum of V
    suffixv<<<dim3(H_, B_), 64>>>(qhi, qlo, sufv);

    // 2) attention -> att hi/lo directly
    attn_wmma<<<dim3(S_ / 128, H_, B_), 256, ASMEM>>>(qhi, qlo, sufv, ahi, alo);

    // 3) y = att @ W_out
    gemm_wmma<0><<<dim3(D_ / BN, MROWS / BM), 256, GSMEM>>>(
        ahi, alo, wohi, wolo, y, nullptr, nullptr, MROWS, D_, D_);

    // 4) out = LN(x + y)
    ln_kernel<<<MROWS, 256>>>(x, y, gamma, beta, out);
}

// round 8
// speedup vs baseline: 2.2586x; 1.3239x over previous
#include <cuda_runtime.h>
#include <cuda_bf16.h>
#include <mma.h>
#include <cstdint>
#include <math.h>

using namespace nvcuda;

#define B_    2
#define S_    2048
#define D_    1024
#define H_    16
#define QKV_  192
#define NQKV  (H_ * QKV_)   /* 3072 */
#define MROWS (B_ * S_)     /* 4096 */

// ---------------- scratch ---------------------------------------------------
__device__ __nv_bfloat16 g_qkvhi[(size_t)MROWS * NQKV];
__device__ __nv_bfloat16 g_qkvlo[(size_t)MROWS * NQKV];
__device__ __nv_bfloat16 g_xhi[(size_t)MROWS * D_];
__device__ __nv_bfloat16 g_xlo[(size_t)MROWS * D_];
__device__ __nv_bfloat16 g_wehi[(size_t)NQKV * D_];   // [N][K]
__device__ __nv_bfloat16 g_welo[(size_t)NQKV * D_];
__device__ __nv_bfloat16 g_wohi[(size_t)D_ * D_];
__device__ __nv_bfloat16 g_wolo[(size_t)D_ * D_];
__device__ __nv_bfloat16 g_ahi[(size_t)MROWS * D_];
__device__ __nv_bfloat16 g_alo[(size_t)MROWS * D_];
__device__ float g_y[(size_t)MROWS * D_];
__device__ float g_sufv[(size_t)B_ * H_ * 33 * 64];

// ---------------- cp.async helpers -----------------------------------------
__device__ __forceinline__ uint32_t smem_u32(const void* p) {
    uint32_t a;
    asm("{ .reg .u64 t; cvta.to.shared.u64 t, %1; cvt.u32.u64 %0, t; }" : "=r"(a) : "l"(p));
    return a;
}
#define CP_ASYNC16(dst, src) \
    asm volatile("cp.async.cg.shared.global [%0], [%1], 16;" :: "r"(dst), "l"(src))
#define CP_COMMIT() asm volatile("cp.async.commit_group;")
#define CP_WAIT0()  asm volatile("cp.async.wait_group 0;")
#define CP_WAIT1()  asm volatile("cp.async.wait_group 1;")

// ---------------------------------------------------------------------------
// HMMA GEMM: C = (Ahi+Alo)[M,K] @ (Bhi+Blo)^T, B stored [N][K].
// 128x128 tile, 256 thr, BK=32, cp.async double-buffered, 2 CTAs/SM.
// ---------------------------------------------------------------------------
#define BM 128
#define BN 128
#define BK 32
#define GP 40
#define MATB (BM * GP * 2)        // 10240 bytes
#define STAGEB (4 * MATB)         // 40960
#define GSMEM (2 * STAGEB)        // 81920

template<int MODE>
__global__ void __launch_bounds__(256, 2) gemm_wmma(
    const __nv_bfloat16* __restrict__ Ahi, const __nv_bfloat16* __restrict__ Alo,
    const __nv_bfloat16* __restrict__ Bhi, const __nv_bfloat16* __restrict__ Blo,
    float* __restrict__ C, __nv_bfloat16* __restrict__ Chi,
    __nv_bfloat16* __restrict__ Clo, int M, int N, int K)
{
    extern __shared__ __align__(16) char smem[];
    const uint32_t sb = smem_u32(smem);
    const int tid = threadIdx.x;
    const int wid = tid >> 5;
    const int wm = wid & 3, wn = wid >> 2;
    const int m0 = blockIdx.y * BM, n0 = blockIdx.x * BN;

    wmma::fragment<wmma::accumulator, 16, 16, 16, float> acc[2][4];
#pragma unroll
    for (int i = 0; i < 2; i++)
#pragma unroll
        for (int j = 0; j < 4; j++) wmma::fill_fragment(acc[i][j], 0.0f);

    const int u0 = tid * 2;
    const int lrow = u0 >> 2;
    const int lcb = (u0 & 3) * 16;         // 0 or 32
    const char* gAh = (const char*)&Ahi[(size_t)(m0 + lrow) * K] + lcb;
    const char* gAl = (const char*)&Alo[(size_t)(m0 + lrow) * K] + lcb;
    const char* gBh = (const char*)&Bhi[(size_t)(n0 + lrow) * K] + lcb;
    const char* gBl = (const char*)&Blo[(size_t)(n0 + lrow) * K] + lcb;
    const uint32_t soff = lrow * (GP * 2) + lcb;

    const int KT = K / BK;
    auto issue = [&](int st, int kt) {
        const uint32_t base = sb + st * STAGEB + soff;
        const size_t gk = (size_t)kt * (BK * 2);
        CP_ASYNC16(base,            gAh + gk);  CP_ASYNC16(base + 16,            gAh + gk + 16);
        CP_ASYNC16(base + MATB,     gAl + gk);  CP_ASYNC16(base + MATB + 16,     gAl + gk + 16);
        CP_ASYNC16(base + 2*MATB,   gBh + gk);  CP_ASYNC16(base + 2*MATB + 16,   gBh + gk + 16);
        CP_ASYNC16(base + 3*MATB,   gBl + gk);  CP_ASYNC16(base + 3*MATB + 16,   gBl + gk + 16);
    };

    issue(0, 0);
    CP_COMMIT();

    for (int kt = 0; kt < KT; kt++) {
        if (kt + 1 < KT) { issue((kt + 1) & 1, kt + 1); CP_COMMIT(); CP_WAIT1(); }
        else             { CP_WAIT0(); }
        __syncthreads();

        const __nv_bfloat16* sAh = (const __nv_bfloat16*)(smem + (kt & 1) * STAGEB);
        const __nv_bfloat16* sAl = sAh + BM * GP;
        const __nv_bfloat16* sBh = sAl + BM * GP;
        const __nv_bfloat16* sBl = sBh + BM * GP;

#pragma unroll
        for (int kk = 0; kk < BK; kk += 16) {
            wmma::fragment<wmma::matrix_b, 16, 16, 16, __nv_bfloat16, wmma::col_major> bh[4], bl[4];
#pragma unroll
            for (int j = 0; j < 4; j++) {
                wmma::load_matrix_sync(bh[j], sBh + (wn * 64 + j * 16) * GP + kk, GP);
                wmma::load_matrix_sync(bl[j], sBl + (wn * 64 + j * 16) * GP + kk, GP);
            }
#pragma unroll
            for (int i = 0; i < 2; i++) {
                wmma::fragment<wmma::matrix_a, 16, 16, 16, __nv_bfloat16, wmma::row_major> ah, al;
                wmma::load_matrix_sync(ah, sAh + (wm * 32 + i * 16) * GP + kk, GP);
                wmma::load_matrix_sync(al, sAl + (wm * 32 + i * 16) * GP + kk, GP);
#pragma unroll
                for (int j = 0; j < 4; j++) {
                    wmma::mma_sync(acc[i][j], ah, bh[j], acc[i][j]);
                    wmma::mma_sync(acc[i][j], ah, bl[j], acc[i][j]);
                    wmma::mma_sync(acc[i][j], al, bh[j], acc[i][j]);
                }
            }
        }
        __syncthreads();
    }

    if (MODE == 0) {
#pragma unroll
        for (int i = 0; i < 2; i++)
#pragma unroll
            for (int j = 0; j < 4; j++)
                wmma::store_matrix_sync(
                    &C[(size_t)(m0 + wm * 32 + i * 16) * N + n0 + wn * 64 + j * 16],
                    acc[i][j], N, wmma::mem_row_major);
    } else {
        float* stage = (float*)smem;
#pragma unroll
        for (int i = 0; i < 2; i++)
#pragma unroll
            for (int j = 0; j < 4; j++)
                wmma::store_matrix_sync(
                    &stage[(size_t)(wm * 32 + i * 16) * BN + wn * 64 + j * 16],
                    acc[i][j], BN, wmma::mem_row_major);
        __syncthreads();
#pragma unroll
        for (int it = 0; it < 16; it++) {
            const int fi = tid + it * 256;
            const int row = fi >> 5, c4 = (fi & 31) * 4;
            float4 v = *(const float4*)&stage[row * BN + c4];
            __nv_bfloat16 h0 = __float2bfloat16(v.x), h1 = __float2bfloat16(v.y);
            __nv_bfloat16 h2 = __float2bfloat16(v.z), h3 = __float2bfloat16(v.w);
            __nv_bfloat162 hA(h0, h1), hB(h2, h3);
            __nv_bfloat162 lA(__float2bfloat16(v.x - __bfloat162float(h0)),
                              __float2bfloat16(v.y - __bfloat162float(h1)));
            __nv_bfloat162 lB(__float2bfloat16(v.z - __bfloat162float(h2)),
                              __float2bfloat16(v.w - __bfloat162float(h3)));
            const size_t o = (size_t)(m0 + row) * N + n0 + c4;
            *(__nv_bfloat162*)&Chi[o] = hA; *(__nv_bfloat162*)&Chi[o + 2] = hB;
            *(__nv_bfloat162*)&Clo[o] = lA; *(__nv_bfloat162*)&Clo[o + 2] = lB;
        }
    }
}

// ---------------------------------------------------------------------------
// f32 -> bf16 hi/lo split
// ---------------------------------------------------------------------------
__global__ void __launch_bounds__(256) split4(const float4* __restrict__ in,
                                              __nv_bfloat162* __restrict__ hi,
                                              __nv_bfloat162* __restrict__ lo,
                                              int n4) {
    int i = blockIdx.x * 256 + threadIdx.x;
    if (i >= n4) return;
    float4 v = in[i];
    __nv_bfloat16 h0 = __float2bfloat16(v.x), h1 = __float2bfloat16(v.y);
    __nv_bfloat16 h2 = __float2bfloat16(v.z), h3 = __float2bfloat16(v.w);
    hi[i * 2 + 0] = __nv_bfloat162(h0, h1);
    hi[i * 2 + 1] = __nv_bfloat162(h2, h3);
    lo[i * 2 + 0] = __nv_bfloat162(__float2bfloat16(v.x - __bfloat162float(h0)),
                                   __float2bfloat16(v.y - __bfloat162float(h1)));
    lo[i * 2 + 1] = __nv_bfloat162(__float2bfloat16(v.z - __bfloat162float(h2)),
                                   __float2bfloat16(v.w - __bfloat162float(h3)));
}

// ---------------------------------------------------------------------------
// W[K,N] f32 -> hi/lo [N,K]
// ---------------------------------------------------------------------------
__global__ void __launch_bounds__(256) transpose_split(const float* __restrict__ W,
                                                       __nv_bfloat16* __restrict__ hi,
                                                       __nv_bfloat16* __restrict__ lo,
                                                       int K, int N) {
    __shared__ float t[32][33];
    const int n0 = blockIdx.x * 32, k0 = blockIdx.y * 32;
    const int x = threadIdx.x, y = threadIdx.y;
#pragma unroll
    for (int i = 0; i < 32; i += 8)
        t[y + i][x] = W[(size_t)(k0 + y + i) * N + n0 + x];
    __syncthreads();
#pragma unroll
    for (int i = 0; i < 32; i += 8) {
        float v = t[x][y + i];
        __nv_bfloat16 h = __float2bfloat16(v);
        size_t o = (size_t)(n0 + y + i) * K + k0 + x;
        hi[o] = h;
        lo[o] = __float2bfloat16(v - __bfloat162float(h));
    }
}

// ---------------------------------------------------------------------------
// V suffix colsum, two stages: per-tile partials, then suffix scan.
// sufv layout: [b][h][33 tiles][64]; after scan sufv[t] = sum over tiles>=t.
// ---------------------------------------------------------------------------
__global__ void __launch_bounds__(64) sufv_partial(const __nv_bfloat16* __restrict__ qhi,
                                                   const __nv_bfloat16* __restrict__ qlo,
                                                   float* __restrict__ sufv) {
    const int t = blockIdx.x, h = blockIdx.y, b = blockIdx.z, d = threadIdx.x;
    const size_t col = (size_t)h * QKV_ + 128 + d;
    float acc = 0.0f;
#pragma unroll 8
    for (int kk = 0; kk < 64; kk++) {
        const size_t o = (size_t)(b * S_ + t * 64 + kk) * NQKV + col;
        acc += __bfloat162float(qhi[o]) + __bfloat162float(qlo[o]);
    }
    sufv[((size_t)(b * H_ + h) * 33 + t) * 64 + d] = acc;
}

__global__ void __launch_bounds__(64) sufv_scan(float* __restrict__ sufv) {
    const int h = blockIdx.x, b = blockIdx.y, d = threadIdx.x;
    float* base = &sufv[((size_t)(b * H_ + h) * 33) * 64 + d];
    float acc = 0.0f;
    base[32 * 64] = 0.0f;
    for (int t = 31; t >= 0; t--) {
        acc += base[t * 64];
        base[t * 64] = acc;
    }
}

// ---------------------------------------------------------------------------
// wmma flash attention, 512 threads (16 warps).
// Q tile 128 rows, K tile 64 keys; key tiles 0 .. 2*qt+1; suffix analytic.
// ---------------------------------------------------------------------------
#define AP 72
#define SFP 68
#define OFF_QH 0
#define OFF_QL (OFF_QH + 128 * AP * 2)
#define OFF_KH (OFF_QL + 128 * AP * 2)
#define OFF_KL (OFF_KH + 64 * AP * 2)
#define OFF_VH (OFF_KL + 64 * AP * 2)
#define OFF_VL (OFF_VH + 64 * AP * 2)
#define OFF_PH (OFF_VL + 64 * AP * 2)
#define OFF_PL (OFF_PH + 128 * AP * 2)
#define OFF_SF (OFF_PL + 128 * AP * 2)
#define OFF_O  (OFF_SF + 128 * SFP * 4)
#define ASMEM  (OFF_O + 128 * 64 * 4)

__global__ void __launch_bounds__(512) attn_wmma(
    const __nv_bfloat16* __restrict__ qkvhi, const __nv_bfloat16* __restrict__ qkvlo,
    const float* __restrict__ sufv,
    __nv_bfloat16* __restrict__ ahi, __nv_bfloat16* __restrict__ alo)
{
    extern __shared__ __align__(16) char smem[];
    __nv_bfloat16* sQh = (__nv_bfloat16*)(smem + OFF_QH);
    __nv_bfloat16* sQl = (__nv_bfloat16*)(smem + OFF_QL);
    __nv_bfloat16* sKh = (__nv_bfloat16*)(smem + OFF_KH);
    __nv_bfloat16* sKl = (__nv_bfloat16*)(smem + OFF_KL);
    __nv_bfloat16* sVh = (__nv_bfloat16*)(smem + OFF_VH);
    __nv_bfloat16* sVl = (__nv_bfloat16*)(smem + OFF_VL);
    __nv_bfloat16* sPh = (__nv_bfloat16*)(smem + OFF_PH);
    __nv_bfloat16* sPl = (__nv_bfloat16*)(smem + OFF_PL);
    float* sSF = (float*)(smem + OFF_SF);
    float* sO  = (float*)(smem + OFF_O);

    const int tid = threadIdx.x, wid = tid >> 5;
    const int wrow = (wid & 7) * 16;       // 16-row tile
    const int wcol = (wid >> 3) * 2;       // first j-frag of the 32-col half
    const int qt = blockIdx.x, h = blockIdx.y, b = blockIdx.z;
    const int q0 = qt * 128;
    const size_t base = (size_t)b * S_ * NQKV + (size_t)h * QKV_;

    // load Q hi/lo (128 x 64): 1024 uint4 per matrix, 512 threads x 2
#pragma unroll
    for (int j = 0; j < 2; j++) {
        const int i = tid + j * 512;
        const int row = i >> 3, c8 = (i & 7) * 8;
        const size_t g = base + (size_t)(q0 + row) * NQKV + c8;
        *(uint4*)&sQh[row * AP + c8] = *(const uint4*)&qkvhi[g];
        *(uint4*)&sQl[row * AP + c8] = *(const uint4*)&qkvlo[g];
    }
    // zero O: 2048 float4
#pragma unroll
    for (int j = 0; j < 4; j++)
        *(float4*)&sO[(tid + j * 512) * 4] = make_float4(0.f, 0.f, 0.f, 0.f);

    const int srow = tid >> 2;            // row owned for softmax/O (0..127)
    const int scb  = (tid & 3) * 16;      // 16-col quarter
    float m = -1e30f, l = 0.0f, alpha = 0.0f;
    const float scale = 0.125f;
    const int gq = q0 + srow;

    const int KTILES = 2 * qt + 2;
    for (int kt = 0; kt < KTILES; kt++) {
        const int k0 = kt * 64;
        __syncthreads();
        // load K,V hi/lo (64 x 64 each): 512 uint4 per matrix, 512 threads x 1
        {
            const int row = tid >> 3, c8 = (tid & 7) * 8;
            const size_t g = base + (size_t)(k0 + row) * NQKV + c8;
            *(uint4*)&sKh[row * AP + c8] = *(const uint4*)&qkvhi[g + 64];
            *(uint4*)&sKl[row * AP + c8] = *(const uint4*)&qkvlo[g + 64];
            *(uint4*)&sVh[row * AP + c8] = *(const uint4*)&qkvhi[g + 128];
            *(uint4*)&sVl[row * AP + c8] = *(const uint4*)&qkvlo[g + 128];
        }
        __syncthreads();

        // S = Q @ K^T  (warp: 16 rows x 32 keys)
        {
            wmma::fragment<wmma::accumulator, 16, 16, 16, float> sacc[2];
#pragma unroll
            for (int j = 0; j < 2; j++) wmma::fill_fragment(sacc[j], 0.0f);
#pragma unroll
            for (int ks = 0; ks < 4; ks++) {
                const int kk = ks * 16;
                wmma::fragment<wmma::matrix_a, 16, 16, 16, __nv_bfloat16, wmma::row_major> ah, al;
                wmma::load_matrix_sync(ah, sQh + wrow * AP + kk, AP);
                wmma::load_matrix_sync(al, sQl + wrow * AP + kk, AP);
#pragma unroll
                for (int j = 0; j < 2; j++) {
                    wmma::fragment<wmma::matrix_b, 16, 16, 16, __nv_bfloat16, wmma::col_major> bh, bl;
                    wmma::load_matrix_sync(bh, sKh + ((wcol + j) * 16) * AP + kk, AP);
                    wmma::load_matrix_sync(bl, sKl + ((wcol + j) * 16) * AP + kk, AP);
                    wmma::mma_sync(sacc[j], ah, bh, sacc[j]);
                    wmma::mma_sync(sacc[j], ah, bl, sacc[j]);
                    wmma::mma_sync(sacc[j], al, bh, sacc[j]);
                }
            }
#pragma unroll
            for (int j = 0; j < 2; j++)
                wmma::store_matrix_sync(&sSF[wrow * SFP + (wcol + j) * 16], sacc[j],
                                        SFP, wmma::mem_row_major);
        }
        __syncthreads();

        // mask + online softmax (4 threads per row, 16 cols each); write P hi/lo
        {
            float s[16];
#pragma unroll
            for (int c4 = 0; c4 < 4; c4++) {
                float4 v = *(const float4*)&sSF[srow * SFP + scb + c4 * 4];
                s[c4 * 4 + 0] = v.x; s[c4 * 4 + 1] = v.y;
                s[c4 * 4 + 2] = v.z; s[c4 * 4 + 3] = v.w;
            }
            const int lim = gq - k0;
#pragma unroll
            for (int c = 0; c < 16; c++) {
                float sv = s[c] * scale;
                if (scb + c > lim) sv = 0.0f;
                s[c] = sv;
            }
            float tmax = s[0];
#pragma unroll
            for (int c = 1; c < 16; c++) tmax = fmaxf(tmax, s[c]);
            tmax = fmaxf(tmax, __shfl_xor_sync(0xffffffffu, tmax, 1));
            tmax = fmaxf(tmax, __shfl_xor_sync(0xffffffffu, tmax, 2));
            const float mn = fmaxf(m, tmax);
            alpha = __expf(m - mn);
            m = mn;
            float ps = 0.0f;
#pragma unroll
            for (int c = 0; c < 16; c++) { s[c] = __expf(s[c] - mn); ps += s[c]; }
            ps += __shfl_xor_sync(0xffffffffu, ps, 1);
            ps += __shfl_xor_sync(0xffffffffu, ps, 2);
            l = l * alpha + ps;
#pragma unroll
            for (int c4 = 0; c4 < 2; c4++) {
                __nv_bfloat16 hh[8], ll[8];
#pragma unroll
                for (int e = 0; e < 8; e++) {
                    const float p = s[c4 * 8 + e];
                    hh[e] = __float2bfloat16(p);
                    ll[e] = __float2bfloat16(p - __bfloat162float(hh[e]));
                }
                *(uint4*)&sPh[srow * AP + scb + c4 * 8] = *(const uint4*)hh;
                *(uint4*)&sPl[srow * AP + scb + c4 * 8] = *(const uint4*)ll;
            }
        }
        __syncthreads();

        // PV = P @ V  (warp: 16 rows x 32 dims)
        {
            wmma::fragment<wmma::accumulator, 16, 16, 16, float> pacc[2];
#pragma unroll
            for (int j = 0; j < 2; j++) wmma::fill_fragment(pacc[j], 0.0f);
#pragma unroll
            for (int ks = 0; ks < 4; ks++) {
                const int kk = ks * 16;
                wmma::fragment<wmma::matrix_a, 16, 16, 16, __nv_bfloat16, wmma::row_major> ah, al;
                wmma::load_matrix_sync(ah, sPh + wrow * AP + kk, AP);
                wmma::load_matrix_sync(al, sPl + wrow * AP + kk, AP);
#pragma unroll
                for (int j = 0; j < 2; j++) {
                    wmma::fragment<wmma::matrix_b, 16, 16, 16, __nv_bfloat16, wmma::row_major> bh, bl;
                    wmma::load_matrix_sync(bh, sVh + kk * AP + (wcol + j) * 16, AP);
                    wmma::load_matrix_sync(bl, sVl + kk * AP + (wcol + j) * 16, AP);
                    wmma::mma_sync(pacc[j], ah, bh, pacc[j]);
                    wmma::mma_sync(pacc[j], ah, bl, pacc[j]);
                    wmma::mma_sync(pacc[j], al, bh, pacc[j]);
                }
            }
#pragma unroll
            for (int j = 0; j < 2; j++)
                wmma::store_matrix_sync(&sSF[wrow * SFP + (wcol + j) * 16], pacc[j],
                                        SFP, wmma::mem_row_major);
        }
        __syncthreads();

        // O = O*alpha + PV (16 cols per thread)
#pragma unroll
        for (int c4 = 0; c4 < 4; c4++) {
            float4 o = *(const float4*)&sO[srow * 64 + scb + c4 * 4];
            float4 p = *(const float4*)&sSF[srow * SFP + scb + c4 * 4];
            o.x = o.x * alpha + p.x; o.y = o.y * alpha + p.y;
            o.z = o.z * alpha + p.z; o.w = o.w * alpha + p.w;
            *(float4*)&sO[srow * 64 + scb + c4 * 4] = o;
        }
    }

    // suffix keys >= 128*(qt+1): logit 0 each
    const int cnt = S_ - 128 * (qt + 1);
    float ofin[16];
#pragma unroll
    for (int c4 = 0; c4 < 4; c4++) {
        float4 o = *(const float4*)&sO[srow * 64 + scb + c4 * 4];
        ofin[c4 * 4 + 0] = o.x; ofin[c4 * 4 + 1] = o.y;
        ofin[c4 * 4 + 2] = o.z; ofin[c4 * 4 + 3] = o.w;
    }
    if (cnt > 0) {
        const float mn = fmaxf(m, 0.0f);
        const float a2 = __expf(m - mn);
        const float e0 = __expf(-mn);
        l = l * a2 + (float)cnt * e0;
        const float* sv = &sufv[((size_t)(b * H_ + h) * 33 + 2 * (qt + 1)) * 64 + scb];
#pragma unroll
        for (int c = 0; c < 16; c++) ofin[c] = ofin[c] * a2 + e0 * sv[c];
    }
    const float inv = 1.0f / l;
    const size_t orow = (size_t)(b * S_ + q0 + srow) * D_ + h * 64 + scb;
#pragma unroll
    for (int c4 = 0; c4 < 2; c4++) {
        __nv_bfloat16 hh[8], ll[8];
#pragma unroll
        for (int e = 0; e < 8; e++) {
            const float v = ofin[c4 * 8 + e] * inv;
            hh[e] = __float2bfloat16(v);
            ll[e] = __float2bfloat16(v - __bfloat162float(hh[e]));
        }
        *(uint4*)&ahi[orow + c4 * 8] = *(const uint4*)hh;
        *(uint4*)&alo[orow + c4 * 8] = *(const uint4*)ll;
    }
}

// ---------------------------------------------------------------------------
// out = LayerNorm(x + y)
// ---------------------------------------------------------------------------
__global__ void __launch_bounds__(256) ln_kernel(const float* __restrict__ x,
                                                 const float* __restrict__ y,
                                                 const float* __restrict__ gamma,
                                                 const float* __restrict__ beta,
                                                 float* __restrict__ out) {
    __shared__ float red[8];
    const int row = blockIdx.x, t = threadIdx.x;
    const int lane = t & 31, wid = t >> 5;
    const size_t off = (size_t)row * D_;

    float v[4], s = 0.0f;
#pragma unroll
    for (int i = 0; i < 4; i++) {
        int idx = t + i * 256;
        v[i] = x[off + idx] + y[off + idx];
        s += v[i];
    }
    for (int d = 16; d > 0; d >>= 1) s += __shfl_xor_sync(0xffffffffu, s, d);
    if (lane == 0) red[wid] = s;
    __syncthreads();
    float tot = 0.0f;
#pragma unroll
    for (int w = 0; w < 8; w++) tot += red[w];
    const float mean = tot * (1.0f / D_);
    __syncthreads();
    float ss = 0.0f;
#pragma unroll
    for (int i = 0; i < 4; i++) { float d = v[i] - mean; ss += d * d; }
    for (int d = 16; d > 0; d >>= 1) ss += __shfl_xor_sync(0xffffffffu, ss, d);
    if (lane == 0) red[wid] = ss;
    __syncthreads();
    float tot2 = 0.0f;
#pragma unroll
    for (int w = 0; w < 8; w++) tot2 += red[w];
    const float rstd = rsqrtf(tot2 * (1.0f / D_) + 1e-3f);
#pragma unroll
    for (int i = 0; i < 4; i++) {
        int idx = t + i * 256;
        out[off + idx] = (v[i] - mean) * rstd * gamma[idx] + beta[idx];
    }
}

// ---------------------------------------------------------------------------
extern "C" void kernel_launch(void* const* d_in, const int* in_sizes, int n_in,
                              void* d_out, int out_size) {
    const float* x       = (const float*)d_in[0];
    const float* W_embed = (const float*)d_in[2];
    const float* W_out   = (const float*)d_in[3];
    const float* gamma   = (const float*)d_in[4];
    const float* beta    = (const float*)d_in[5];
    float* out = (float*)d_out;

    __nv_bfloat16 *qhi, *qlo, *xhi, *xlo, *wehi, *welo, *wohi, *wolo, *ahi, *alo;
    float *y, *sufv;
    cudaGetSymbolAddress((void**)&qhi,  g_qkvhi);
    cudaGetSymbolAddress((void**)&qlo,  g_qkvlo);
    cudaGetSymbolAddress((void**)&xhi,  g_xhi);
    cudaGetSymbolAddress((void**)&xlo,  g_xlo);
    cudaGetSymbolAddress((void**)&wehi, g_wehi);
    cudaGetSymbolAddress((void**)&welo, g_welo);
    cudaGetSymbolAddress((void**)&wohi, g_wohi);
    cudaGetSymbolAddress((void**)&wolo, g_wolo);
    cudaGetSymbolAddress((void**)&ahi,  g_ahi);
    cudaGetSymbolAddress((void**)&alo,  g_alo);
    cudaGetSymbolAddress((void**)&y,    g_y);
    cudaGetSymbolAddress((void**)&sufv, g_sufv);

    cudaFuncSetAttribute(gemm_wmma<0>, cudaFuncAttributeMaxDynamicSharedMemorySize, GSMEM);
    cudaFuncSetAttribute(gemm_wmma<1>, cudaFuncAttributeMaxDynamicSharedMemorySize, GSMEM);
    cudaFuncSetAttribute(attn_wmma, cudaFuncAttributeMaxDynamicSharedMemorySize, ASMEM);

    // 0) splits / transposes
    split4<<<(MROWS * D_ / 4 + 255) / 256, 256>>>((const float4*)x,
        (__nv_bfloat162*)xhi, (__nv_bfloat162*)xlo, MROWS * D_ / 4);
    transpose_split<<<dim3(NQKV / 32, D_ / 32), dim3(32, 8)>>>(W_embed, wehi, welo, D_, NQKV);
    transpose_split<<<dim3(D_ / 32, D_ / 32), dim3(32, 8)>>>(W_out, wohi, wolo, D_, D_);

    // 1) qkv = x @ W_embed -> bf16 hi/lo directly
    gemm_wmma<1><<<dim3(NQKV / BN, MROWS / BM), 256, GSMEM>>>(
        xhi, xlo, wehi, welo, nullptr, qhi, qlo, MROWS, NQKV, D_);

    // 1b) suffix colsum of V (parallel partials + tiny scan)
    sufv_partial<<<dim3(32, H_, B_), 64>>>(qhi, qlo, sufv);
    sufv_scan<<<dim3(H_, B_), 64>>>(sufv);

    // 2) attention -> att hi/lo directly
    attn_wmma<<<dim3(S_ / 128, H_, B_), 512, ASMEM>>>(qhi, qlo, sufv, ahi, alo);

    // 3) y = att @ W_out
    gemm_wmma<0><<<dim3(D_ / BN, MROWS / BM), 256, GSMEM>>>(
        ahi, alo, wohi, wolo, y, nullptr, nullptr, MROWS, D_, D_);

    // 4) out = LN(x + y)
    ln_kernel<<<MROWS, 256>>>(x, y, gamma, beta, out);
}

// round 9
// speedup vs baseline: 2.5570x; 1.1322x over previous
#include <cuda_runtime.h>
#include <cuda_bf16.h>
#include <mma.h>
#include <cstdint>
#include <math.h>

using namespace nvcuda;

#define B_    2
#define S_    2048
#define D_    1024
#define H_    16
#define QKV_  192
#define NQKV  (H_ * QKV_)   /* 3072 */
#define MROWS (B_ * S_)     /* 4096 */

// ---------------- scratch ---------------------------------------------------
__device__ __nv_bfloat16 g_qkvhi[(size_t)MROWS * NQKV];
__device__ __nv_bfloat16 g_qkvlo[(size_t)MROWS * NQKV];
__device__ __nv_bfloat16 g_xhi[(size_t)MROWS * D_];
__device__ __nv_bfloat16 g_xlo[(size_t)MROWS * D_];
__device__ __nv_bfloat16 g_wehi[(size_t)NQKV * D_];   // [N][K]
__device__ __nv_bfloat16 g_welo[(size_t)NQKV * D_];
__device__ __nv_bfloat16 g_wohi[(size_t)D_ * D_];
__device__ __nv_bfloat16 g_wolo[(size_t)D_ * D_];
__device__ __nv_bfloat16 g_ahi[(size_t)MROWS * D_];
__device__ __nv_bfloat16 g_alo[(size_t)MROWS * D_];
__device__ float g_y[(size_t)MROWS * D_];
__device__ float g_sufv[(size_t)B_ * H_ * 33 * 64];

// ---------------- cp.async helpers -----------------------------------------
__device__ __forceinline__ uint32_t smem_u32(const void* p) {
    uint32_t a;
    asm("{ .reg .u64 t; cvta.to.shared.u64 t, %1; cvt.u32.u64 %0, t; }" : "=r"(a) : "l"(p));
    return a;
}
#define CP_ASYNC16(dst, src) \
    asm volatile("cp.async.cg.shared.global [%0], [%1], 16;" :: "r"(dst), "l"(src))
#define CP_COMMIT() asm volatile("cp.async.commit_group;")
#define CP_WAIT0()  asm volatile("cp.async.wait_group 0;")
#define CP_WAIT1()  asm volatile("cp.async.wait_group 1;")

// ---------------------------------------------------------------------------
// HMMA GEMM (unchanged from R8): 128x128 tile, 256 thr, BK=32, 2 CTAs/SM.
// ---------------------------------------------------------------------------
#define BM 128
#define BN 128
#define BK 32
#define GP 40
#define MATB (BM * GP * 2)
#define STAGEB (4 * MATB)
#define GSMEM (2 * STAGEB)

template<int MODE>
__global__ void __launch_bounds__(256, 2) gemm_wmma(
    const __nv_bfloat16* __restrict__ Ahi, const __nv_bfloat16* __restrict__ Alo,
    const __nv_bfloat16* __restrict__ Bhi, const __nv_bfloat16* __restrict__ Blo,
    float* __restrict__ C, __nv_bfloat16* __restrict__ Chi,
    __nv_bfloat16* __restrict__ Clo, int M, int N, int K)
{
    extern __shared__ __align__(16) char smem[];
    const uint32_t sb = smem_u32(smem);
    const int tid = threadIdx.x;
    const int wid = tid >> 5;
    const int wm = wid & 3, wn = wid >> 2;
    const int m0 = blockIdx.y * BM, n0 = blockIdx.x * BN;

    wmma::fragment<wmma::accumulator, 16, 16, 16, float> acc[2][4];
#pragma unroll
    for (int i = 0; i < 2; i++)
#pragma unroll
        for (int j = 0; j < 4; j++) wmma::fill_fragment(acc[i][j], 0.0f);

    const int u0 = tid * 2;
    const int lrow = u0 >> 2;
    const int lcb = (u0 & 3) * 16;
    const char* gAh = (const char*)&Ahi[(size_t)(m0 + lrow) * K] + lcb;
    const char* gAl = (const char*)&Alo[(size_t)(m0 + lrow) * K] + lcb;
    const char* gBh = (const char*)&Bhi[(size_t)(n0 + lrow) * K] + lcb;
    const char* gBl = (const char*)&Blo[(size_t)(n0 + lrow) * K] + lcb;
    const uint32_t soff = lrow * (GP * 2) + lcb;

    const int KT = K / BK;
    auto issue = [&](int st, int kt) {
        const uint32_t base = sb + st * STAGEB + soff;
        const size_t gk = (size_t)kt * (BK * 2);
        CP_ASYNC16(base,            gAh + gk);  CP_ASYNC16(base + 16,            gAh + gk + 16);
        CP_ASYNC16(base + MATB,     gAl + gk);  CP_ASYNC16(base + MATB + 16,     gAl + gk + 16);
        CP_ASYNC16(base + 2*MATB,   gBh + gk);  CP_ASYNC16(base + 2*MATB + 16,   gBh + gk + 16);
        CP_ASYNC16(base + 3*MATB,   gBl + gk);  CP_ASYNC16(base + 3*MATB + 16,   gBl + gk + 16);
    };

    issue(0, 0);
    CP_COMMIT();

    for (int kt = 0; kt < KT; kt++) {
        if (kt + 1 < KT) { issue((kt + 1) & 1, kt + 1); CP_COMMIT(); CP_WAIT1(); }
        else             { CP_WAIT0(); }
        __syncthreads();

        const __nv_bfloat16* sAh = (const __nv_bfloat16*)(smem + (kt & 1) * STAGEB);
        const __nv_bfloat16* sAl = sAh + BM * GP;
        const __nv_bfloat16* sBh = sAl + BM * GP;
        const __nv_bfloat16* sBl = sBh + BM * GP;

#pragma unroll
        for (int kk = 0; kk < BK; kk += 16) {
            wmma::fragment<wmma::matrix_b, 16, 16, 16, __nv_bfloat16, wmma::col_major> bh[4], bl[4];
#pragma unroll
            for (int j = 0; j < 4; j++) {
                wmma::load_matrix_sync(bh[j], sBh + (wn * 64 + j * 16) * GP + kk, GP);
                wmma::load_matrix_sync(bl[j], sBl + (wn * 64 + j * 16) * GP + kk, GP);
            }
#pragma unroll
            for (int i = 0; i < 2; i++) {
                wmma::fragment<wmma::matrix_a, 16, 16, 16, __nv_bfloat16, wmma::row_major> ah, al;
                wmma::load_matrix_sync(ah, sAh + (wm * 32 + i * 16) * GP + kk, GP);
                wmma::load_matrix_sync(al, sAl + (wm * 32 + i * 16) * GP + kk, GP);
#pragma unroll
                for (int j = 0; j < 4; j++) {
                    wmma::mma_sync(acc[i][j], ah, bh[j], acc[i][j]);
                    wmma::mma_sync(acc[i][j], ah, bl[j], acc[i][j]);
                    wmma::mma_sync(acc[i][j], al, bh[j], acc[i][j]);
                }
            }
        }
        __syncthreads();
    }

    if (MODE == 0) {
#pragma unroll
        for (int i = 0; i < 2; i++)
#pragma unroll
            for (int j = 0; j < 4; j++)
                wmma::store_matrix_sync(
                    &C[(size_t)(m0 + wm * 32 + i * 16) * N + n0 + wn * 64 + j * 16],
                    acc[i][j], N, wmma::mem_row_major);
    } else {
        float* stage = (float*)smem;
#pragma unroll
        for (int i = 0; i < 2; i++)
#pragma unroll
            for (int j = 0; j < 4; j++)
                wmma::store_matrix_sync(
                    &stage[(size_t)(wm * 32 + i * 16) * BN + wn * 64 + j * 16],
                    acc[i][j], BN, wmma::mem_row_major);
        __syncthreads();
#pragma unroll
        for (int it = 0; it < 16; it++) {
            const int fi = tid + it * 256;
            const int row = fi >> 5, c4 = (fi & 31) * 4;
            float4 v = *(const float4*)&stage[row * BN + c4];
            __nv_bfloat16 h0 = __float2bfloat16(v.x), h1 = __float2bfloat16(v.y);
            __nv_bfloat16 h2 = __float2bfloat16(v.z), h3 = __float2bfloat16(v.w);
            __nv_bfloat162 hA(h0, h1), hB(h2, h3);
            __nv_bfloat162 lA(__float2bfloat16(v.x - __bfloat162float(h0)),
                              __float2bfloat16(v.y - __bfloat162float(h1)));
            __nv_bfloat162 lB(__float2bfloat16(v.z - __bfloat162float(h2)),
                              __float2bfloat16(v.w - __bfloat162float(h3)));
            const size_t o = (size_t)(m0 + row) * N + n0 + c4;
            *(__nv_bfloat162*)&Chi[o] = hA; *(__nv_bfloat162*)&Chi[o + 2] = hB;
            *(__nv_bfloat162*)&Clo[o] = lA; *(__nv_bfloat162*)&Clo[o + 2] = lB;
        }
    }
}

// ---------------------------------------------------------------------------
__global__ void __launch_bounds__(256) split4(const float4* __restrict__ in,
                                              __nv_bfloat162* __restrict__ hi,
                                              __nv_bfloat162* __restrict__ lo,
                                              int n4) {
    int i = blockIdx.x * 256 + threadIdx.x;
    if (i >= n4) return;
    float4 v = in[i];
    __nv_bfloat16 h0 = __float2bfloat16(v.x), h1 = __float2bfloat16(v.y);
    __nv_bfloat16 h2 = __float2bfloat16(v.z), h3 = __float2bfloat16(v.w);
    hi[i * 2 + 0] = __nv_bfloat162(h0, h1);
    hi[i * 2 + 1] = __nv_bfloat162(h2, h3);
    lo[i * 2 + 0] = __nv_bfloat162(__float2bfloat16(v.x - __bfloat162float(h0)),
                                   __float2bfloat16(v.y - __bfloat162float(h1)));
    lo[i * 2 + 1] = __nv_bfloat162(__float2bfloat16(v.z - __bfloat162float(h2)),
                                   __float2bfloat16(v.w - __bfloat162float(h3)));
}

__global__ void __launch_bounds__(256) transpose_split(const float* __restrict__ W,
                                                       __nv_bfloat16* __restrict__ hi,
                                                       __nv_bfloat16* __restrict__ lo,
                                                       int K, int N) {
    __shared__ float t[32][33];
    const int n0 = blockIdx.x * 32, k0 = blockIdx.y * 32;
    const int x = threadIdx.x, y = threadIdx.y;
#pragma unroll
    for (int i = 0; i < 32; i += 8)
        t[y + i][x] = W[(size_t)(k0 + y + i) * N + n0 + x];
    __syncthreads();
#pragma unroll
    for (int i = 0; i < 32; i += 8) {
        float v = t[x][y + i];
        __nv_bfloat16 h = __float2bfloat16(v);
        size_t o = (size_t)(n0 + y + i) * K + k0 + x;
        hi[o] = h;
        lo[o] = __float2bfloat16(v - __bfloat162float(h));
    }
}

// ---------------------------------------------------------------------------
__global__ void __launch_bounds__(64) sufv_partial(const __nv_bfloat16* __restrict__ qhi,
                                                   const __nv_bfloat16* __restrict__ qlo,
                                                   float* __restrict__ sufv) {
    const int t = blockIdx.x, h = blockIdx.y, b = blockIdx.z, d = threadIdx.x;
    const size_t col = (size_t)h * QKV_ + 128 + d;
    float acc = 0.0f;
#pragma unroll 8
    for (int kk = 0; kk < 64; kk++) {
        const size_t o = (size_t)(b * S_ + t * 64 + kk) * NQKV + col;
        acc += __bfloat162float(qhi[o]) + __bfloat162float(qlo[o]);
    }
    sufv[((size_t)(b * H_ + h) * 33 + t) * 64 + d] = acc;
}

__global__ void __launch_bounds__(64) sufv_scan(float* __restrict__ sufv) {
    const int h = blockIdx.x, b = blockIdx.y, d = threadIdx.x;
    float* base = &sufv[((size_t)(b * H_ + h) * 33) * 64 + d];
    float acc = 0.0f;
    base[32 * 64] = 0.0f;
    for (int t = 31; t >= 0; t--) {
        acc += base[t * 64];
        base[t * 64] = acc;
    }
}

// ---------------------------------------------------------------------------
// wmma flash attention, 512 threads. cp.async double-buffered K/V stages,
// O in registers, heavy query blocks scheduled first.
// ---------------------------------------------------------------------------
#define AP 72
#define SFP 68
#define AQH 0
#define AQL (AQH + 128 * AP * 2)                 /* 18432 */
#define AKV (AQL + 128 * AP * 2)                 /* 36864: KV stages base */
#define KVMAT (64 * AP * 2)                      /* 9216 per matrix */
#define KVSTAGE (4 * KVMAT)                      /* 36864 per stage */
#define APH (AKV + 2 * KVSTAGE)                  /* 110592 */
#define APL (APH + 128 * AP * 2)
#define ASF (APL + 128 * AP * 2)                 /* 147456 */
#define ASMEM (ASF + 128 * SFP * 4)              /* 182272 */

__global__ void __launch_bounds__(512) attn_wmma(
    const __nv_bfloat16* __restrict__ qkvhi, const __nv_bfloat16* __restrict__ qkvlo,
    const float* __restrict__ sufv,
    __nv_bfloat16* __restrict__ ahi, __nv_bfloat16* __restrict__ alo)
{
    extern __shared__ __align__(16) char smem[];
    const uint32_t sb = smem_u32(smem);
    __nv_bfloat16* sQh = (__nv_bfloat16*)(smem + AQH);
    __nv_bfloat16* sQl = (__nv_bfloat16*)(smem + AQL);
    __nv_bfloat16* sPh = (__nv_bfloat16*)(smem + APH);
    __nv_bfloat16* sPl = (__nv_bfloat16*)(smem + APL);
    float* sSF = (float*)(smem + ASF);

    const int tid = threadIdx.x, wid = tid >> 5;
    const int wrow = (wid & 7) * 16;
    const int wcol = (wid >> 3) * 2;
    const int qt = gridDim.x - 1 - blockIdx.x;     // heavy blocks first
    const int h = blockIdx.y, b = blockIdx.z;
    const int q0 = qt * 128;
    const size_t base = (size_t)b * S_ * NQKV + (size_t)h * QKV_;

    // K/V cp.async loader: per thread one uint4 per matrix
    const int krow = tid >> 3, kc8 = (tid & 7) * 8;
    const uint32_t kvoff = (uint32_t)(krow * AP + kc8) * 2;
    auto issue_kv = [&](int st, int kt) {
        const uint32_t stb = sb + AKV + st * KVSTAGE + kvoff;
        const char* gh = (const char*)(qkvhi + base + (size_t)(kt * 64 + krow) * NQKV + kc8);
        const char* gl = (const char*)(qkvlo + base + (size_t)(kt * 64 + krow) * NQKV + kc8);
        CP_ASYNC16(stb,             gh + 128);   // K hi  (+64 elements)
        CP_ASYNC16(stb + KVMAT,     gl + 128);   // K lo
        CP_ASYNC16(stb + 2*KVMAT,   gh + 256);   // V hi  (+128 elements)
        CP_ASYNC16(stb + 3*KVMAT,   gl + 256);   // V lo
    };

    // load Q hi/lo (128 x 64)
#pragma unroll
    for (int j = 0; j < 2; j++) {
        const int i = tid + j * 512;
        const int row = i >> 3, c8 = (i & 7) * 8;
        const size_t g = base + (size_t)(q0 + row) * NQKV + c8;
        *(uint4*)&sQh[row * AP + c8] = *(const uint4*)&qkvhi[g];
        *(uint4*)&sQl[row * AP + c8] = *(const uint4*)&qkvlo[g];
    }

    const int srow = tid >> 2;
    const int scb  = (tid & 3) * 16;
    float m = -1e30f, l = 0.0f, alpha = 0.0f;
    float o[16];
#pragma unroll
    for (int c = 0; c < 16; c++) o[c] = 0.0f;
    const float scale = 0.125f;
    const int gq = q0 + srow;

    const int KTILES = 2 * qt + 2;
    issue_kv(0, 0);
    CP_COMMIT();

    for (int kt = 0; kt < KTILES; kt++) {
        const int st = kt & 1;
        const int k0 = kt * 64;
        // prefetch next tile into the other stage (safe: PV of kt-1 done
        // before every thread passed the post-PV barrier of iter kt-1)
        if (kt + 1 < KTILES) { issue_kv(st ^ 1, kt + 1); CP_COMMIT(); CP_WAIT1(); }
        else                 { CP_WAIT0(); }
        __syncthreads();

        const __nv_bfloat16* sKh = (const __nv_bfloat16*)(smem + AKV + st * KVSTAGE);
        const __nv_bfloat16* sKl = sKh + 64 * AP;
        const __nv_bfloat16* sVh = sKl + 64 * AP;
        const __nv_bfloat16* sVl = sVh + 64 * AP;

        // S = Q @ K^T  (warp: 16 rows x 32 keys)
        {
            wmma::fragment<wmma::accumulator, 16, 16, 16, float> sacc[2];
#pragma unroll
            for (int j = 0; j < 2; j++) wmma::fill_fragment(sacc[j], 0.0f);
#pragma unroll
            for (int ks = 0; ks < 4; ks++) {
                const int kk = ks * 16;
                wmma::fragment<wmma::matrix_a, 16, 16, 16, __nv_bfloat16, wmma::row_major> ah, al;
                wmma::load_matrix_sync(ah, sQh + wrow * AP + kk, AP);
                wmma::load_matrix_sync(al, sQl + wrow * AP + kk, AP);
#pragma unroll
                for (int j = 0; j < 2; j++) {
                    wmma::fragment<wmma::matrix_b, 16, 16, 16, __nv_bfloat16, wmma::col_major> bh, bl;
                    wmma::load_matrix_sync(bh, sKh + ((wcol + j) * 16) * AP + kk, AP);
                    wmma::load_matrix_sync(bl, sKl + ((wcol + j) * 16) * AP + kk, AP);
                    wmma::mma_sync(sacc[j], ah, bh, sacc[j]);
                    wmma::mma_sync(sacc[j], ah, bl, sacc[j]);
                    wmma::mma_sync(sacc[j], al, bh, sacc[j]);
                }
            }
#pragma unroll
            for (int j = 0; j < 2; j++)
                wmma::store_matrix_sync(&sSF[wrow * SFP + (wcol + j) * 16], sacc[j],
                                        SFP, wmma::mem_row_major);
        }
        __syncthreads();

        // mask + online softmax; write P hi/lo
        {
            float s[16];
#pragma unroll
            for (int c4 = 0; c4 < 4; c4++) {
                float4 v = *(const float4*)&sSF[srow * SFP + scb + c4 * 4];
                s[c4 * 4 + 0] = v.x; s[c4 * 4 + 1] = v.y;
                s[c4 * 4 + 2] = v.z; s[c4 * 4 + 3] = v.w;
            }
            const int lim = gq - k0;
#pragma unroll
            for (int c = 0; c < 16; c++) {
                float sv = s[c] * scale;
                if (scb + c > lim) sv = 0.0f;
                s[c] = sv;
            }
            float tmax = s[0];
#pragma unroll
            for (int c = 1; c < 16; c++) tmax = fmaxf(tmax, s[c]);
            tmax = fmaxf(tmax, __shfl_xor_sync(0xffffffffu, tmax, 1));
            tmax = fmaxf(tmax, __shfl_xor_sync(0xffffffffu, tmax, 2));
            const float mn = fmaxf(m, tmax);
            alpha = __expf(m - mn);
            m = mn;
            float ps = 0.0f;
#pragma unroll
            for (int c = 0; c < 16; c++) { s[c] = __expf(s[c] - mn); ps += s[c]; }
            ps += __shfl_xor_sync(0xffffffffu, ps, 1);
            ps += __shfl_xor_sync(0xffffffffu, ps, 2);
            l = l * alpha + ps;
#pragma unroll
            for (int c4 = 0; c4 < 2; c4++) {
                __nv_bfloat16 hh[8], ll[8];
#pragma unroll
                for (int e = 0; e < 8; e++) {
                    const float p = s[c4 * 8 + e];
                    hh[e] = __float2bfloat16(p);
                    ll[e] = __float2bfloat16(p - __bfloat162float(hh[e]));
                }
                *(uint4*)&sPh[srow * AP + scb + c4 * 8] = *(const uint4*)hh;
                *(uint4*)&sPl[srow * AP + scb + c4 * 8] = *(const uint4*)ll;
            }
        }
        __syncthreads();

        // PV = P @ V  (warp: 16 rows x 32 dims)
        {
            wmma::fragment<wmma::accumulator, 16, 16, 16, float> pacc[2];
#pragma unroll
            for (int j = 0; j < 2; j++) wmma::fill_fragment(pacc[j], 0.0f);
#pragma unroll
            for (int ks = 0; ks < 4; ks++) {
                const int kk = ks * 16;
                wmma::fragment<wmma::matrix_a, 16, 16, 16, __nv_bfloat16, wmma::row_major> ah, al;
                wmma::load_matrix_sync(ah, sPh + wrow * AP + kk, AP);
                wmma::load_matrix_sync(al, sPl + wrow * AP + kk, AP);
#pragma unroll
                for (int j = 0; j < 2; j++) {
                    wmma::fragment<wmma::matrix_b, 16, 16, 16, __nv_bfloat16, wmma::row_major> bh, bl;
                    wmma::load_matrix_sync(bh, sVh + kk * AP + (wcol + j) * 16, AP);
                    wmma::load_matrix_sync(bl, sVl + kk * AP + (wcol + j) * 16, AP);
                    wmma::mma_sync(pacc[j], ah, bh, pacc[j]);
                    wmma::mma_sync(pacc[j], ah, bl, pacc[j]);
                    wmma::mma_sync(pacc[j], al, bh, pacc[j]);
                }
            }
#pragma unroll
            for (int j = 0; j < 2; j++)
                wmma::store_matrix_sync(&sSF[wrow * SFP + (wcol + j) * 16], pacc[j],
                                        SFP, wmma::mem_row_major);
        }
        __syncthreads();

        // O(reg) = O*alpha + PV
#pragma unroll
        for (int c4 = 0; c4 < 4; c4++) {
            float4 p = *(const float4*)&sSF[srow * SFP + scb + c4 * 4];
            o[c4 * 4 + 0] = o[c4 * 4 + 0] * alpha + p.x;
            o[c4 * 4 + 1] = o[c4 * 4 + 1] * alpha + p.y;
            o[c4 * 4 + 2] = o[c4 * 4 + 2] * alpha + p.z;
            o[c4 * 4 + 3] = o[c4 * 4 + 3] * alpha + p.w;
        }
    }

    // suffix keys >= 128*(qt+1): logit 0 each
    const int cnt = S_ - 128 * (qt + 1);
    if (cnt > 0) {
        const float mn = fmaxf(m, 0.0f);
        const float a2 = __expf(m - mn);
        const float e0 = __expf(-mn);
        l = l * a2 + (float)cnt * e0;
        const float* sv = &sufv[((size_t)(b * H_ + h) * 33 + 2 * (qt + 1)) * 64 + scb];
#pragma unroll
        for (int c = 0; c < 16; c++) o[c] = o[c] * a2 + e0 * sv[c];
    }
    const float inv = 1.0f / l;
    const size_t orow = (size_t)(b * S_ + q0 + srow) * D_ + h * 64 + scb;
#pragma unroll
    for (int c4 = 0; c4 < 2; c4++) {
        __nv_bfloat16 hh[8], ll[8];
#pragma unroll
        for (int e = 0; e < 8; e++) {
            const float v = o[c4 * 8 + e] * inv;
            hh[e] = __float2bfloat16(v);
            ll[e] = __float2bfloat16(v - __bfloat162float(hh[e]));
        }
        *(uint4*)&ahi[orow + c4 * 8] = *(const uint4*)hh;
        *(uint4*)&alo[orow + c4 * 8] = *(const uint4*)ll;
    }
}

// ---------------------------------------------------------------------------
__global__ void __launch_bounds__(256) ln_kernel(const float* __restrict__ x,
                                                 const float* __restrict__ y,
                                                 const float* __restrict__ gamma,
                                                 const float* __restrict__ beta,
                                                 float* __restrict__ out) {
    __shared__ float red[8];
    const int row = blockIdx.x, t = threadIdx.x;
    const int lane = t & 31, wid = t >> 5;
    const size_t off = (size_t)row * D_;

    float v[4], s = 0.0f;
#pragma unroll
    for (int i = 0; i < 4; i++) {
        int idx = t + i * 256;
        v[i] = x[off + idx] + y[off + idx];
        s += v[i];
    }
    for (int d = 16; d > 0; d >>= 1) s += __shfl_xor_sync(0xffffffffu, s, d);
    if (lane == 0) red[wid] = s;
    __syncthreads();
    float tot = 0.0f;
#pragma unroll
    for (int w = 0; w < 8; w++) tot += red[w];
    const float mean = tot * (1.0f / D_);
    __syncthreads();
    float ss = 0.0f;
#pragma unroll
    for (int i = 0; i < 4; i++) { float d = v[i] - mean; ss += d * d; }
    for (int d = 16; d > 0; d >>= 1) ss += __shfl_xor_sync(0xffffffffu, ss, d);
    if (lane == 0) red[wid] = ss;
    __syncthreads();
    float tot2 = 0.0f;
#pragma unroll
    for (int w = 0; w < 8; w++) tot2 += red[w];
    const float rstd = rsqrtf(tot2 * (1.0f / D_) + 1e-3f);
#pragma unroll
    for (int i = 0; i < 4; i++) {
        int idx = t + i * 256;
        out[off + idx] = (v[i] - mean) * rstd * gamma[idx] + beta[idx];
    }
}

// ---------------------------------------------------------------------------
extern "C" void kernel_launch(void* const* d_in, const int* in_sizes, int n_in,
                              void* d_out, int out_size) {
    const float* x       = (const float*)d_in[0];
    const float* W_embed = (const float*)d_in[2];
    const float* W_out   = (const float*)d_in[3];
    const float* gamma   = (const float*)d_in[4];
    const float* beta    = (const float*)d_in[5];
    float* out = (float*)d_out;

    __nv_bfloat16 *qhi, *qlo, *xhi, *xlo, *wehi, *welo, *wohi, *wolo, *ahi, *alo;
    float *y, *sufv;
    cudaGetSymbolAddress((void**)&qhi,  g_qkvhi);
    cudaGetSymbolAddress((void**)&qlo,  g_qkvlo);
    cudaGetSymbolAddress((void**)&xhi,  g_xhi);
    cudaGetSymbolAddress((void**)&xlo,  g_xlo);
    cudaGetSymbolAddress((void**)&wehi, g_wehi);
    cudaGetSymbolAddress((void**)&welo, g_welo);
    cudaGetSymbolAddress((void**)&wohi, g_wohi);
    cudaGetSymbolAddress((void**)&wolo, g_wolo);
    cudaGetSymbolAddress((void**)&ahi,  g_ahi);
    cudaGetSymbolAddress((void**)&alo,  g_alo);
    cudaGetSymbolAddress((void**)&y,    g_y);
    cudaGetSymbolAddress((void**)&sufv, g_sufv);

    cudaFuncSetAttribute(gemm_wmma<0>, cudaFuncAttributeMaxDynamicSharedMemorySize, GSMEM);
    cudaFuncSetAttribute(gemm_wmma<1>, cudaFuncAttributeMaxDynamicSharedMemorySize, GSMEM);
    cudaFuncSetAttribute(attn_wmma, cudaFuncAttributeMaxDynamicSharedMemorySize, ASMEM);

    split4<<<(MROWS * D_ / 4 + 255) / 256, 256>>>((const float4*)x,
        (__nv_bfloat162*)xhi, (__nv_bfloat162*)xlo, MROWS * D_ / 4);
    transpose_split<<<dim3(NQKV / 32, D_ / 32), dim3(32, 8)>>>(W_embed, wehi, welo, D_, NQKV);
    transpose_split<<<dim3(D_ / 32, D_ / 32), dim3(32, 8)>>>(W_out, wohi, wolo, D_, D_);

    gemm_wmma<1><<<dim3(NQKV / BN, MROWS / BM), 256, GSMEM>>>(
        xhi, xlo, wehi, welo, nullptr, qhi, qlo, MROWS, NQKV, D_);

    sufv_partial<<<dim3(32, H_, B_), 64>>>(qhi, qlo, sufv);
    sufv_scan<<<dim3(H_, B_), 64>>>(sufv);

    attn_wmma<<<dim3(S_ / 128, H_, B_), 512, ASMEM>>>(qhi, qlo, sufv, ahi, alo);

    gemm_wmma<0><<<dim3(D_ / BN, MROWS / BM), 256, GSMEM>>>(
        ahi, alo, wohi, wolo, y, nullptr, nullptr, MROWS, D_, D_);

    ln_kernel<<<MROWS, 256>>>(x, y, gamma, beta, out);
}